// round 11
// baseline (speedup 1.0000x reference)
#include <cuda_runtime.h>

#define TN (1 << 20)
#define LOG2TN 20
#define KM 3
#define C_ALPHA 2000.0f
#define C_TAU 1e-7f
#define C_TAU2 1e-14f
#define PI_D 3.14159265358979323846

typedef unsigned long long ull;

// ---------------- scratch (device globals; no allocation allowed) ----------------
__device__ float2 g_A[2 * TN];        // FFT ping buffer (2 batches)
__device__ float2 g_Bb[2 * TN];       // FFT pong buffer; [0..TN) holds fhat after fwd
__device__ float2 g_lamPrev[TN];      // lambda stash / final lambda
struct __align__(128) Acc4Blk { double a[4][16]; };   // 4 slots x (8 used + pad to 128B)
__device__ Acc4Blk g_acc4;            // monotone accumulators, 4-way split by blockIdx&3
struct __align__(128) CtrBlk { unsigned c; unsigned pad[31]; };
__device__ CtrBlk g_ctrB;             // arrival counter (own line)
struct __align__(128) GoBlk { volatile unsigned g; unsigned pad[31]; };
__device__ GoBlk g_goB;               // release word (own line)
__device__ float g_om[KM];

__device__ __forceinline__ float frcp(float x) {
    float r; asm("rcp.approx.f32 %0, %1;" : "=f"(r) : "f"(x)); return r;
}

// ---------------- packed f32x2 helpers ----------------
__device__ __forceinline__ ull pk(float lo, float hi) {
    ull r; asm("mov.b64 %0, {%1, %2};" : "=l"(r) : "f"(lo), "f"(hi)); return r;
}
__device__ __forceinline__ void upk(float& lo, float& hi, ull v) {
    asm("mov.b64 {%0, %1}, %2;" : "=f"(lo), "=f"(hi) : "l"(v));
}
__device__ __forceinline__ ull fma2(ull a, ull b, ull c) {
    ull d; asm("fma.rn.f32x2 %0, %1, %2, %3;" : "=l"(d) : "l"(a), "l"(b), "l"(c)); return d;
}
__device__ __forceinline__ ull add2(ull a, ull b) {
    ull d; asm("add.rn.f32x2 %0, %1, %2;" : "=l"(d) : "l"(a), "l"(b)); return d;
}
__device__ __forceinline__ ull mul2(ull a, ull b) {
    ull d; asm("mul.rn.f32x2 %0, %1, %2;" : "=l"(d) : "l"(a), "l"(b)); return d;
}
__device__ __forceinline__ ull rcp2(ull a) {
    float lo, hi; upk(lo, hi, a); return pk(frcp(lo), frcp(hi));
}

// ---------------- complex helpers ----------------
__device__ __forceinline__ float2 cadd(float2 a, float2 b) { return make_float2(a.x + b.x, a.y + b.y); }
__device__ __forceinline__ float2 csub(float2 a, float2 b) { return make_float2(a.x - b.x, a.y - b.y); }
__device__ __forceinline__ float2 cmul(float2 a, float2 b) {
    return make_float2(a.x * b.x - a.y * b.y, a.x * b.y + a.y * b.x);
}

// ---------------- radix-16 butterfly ----------------
template <bool FWD>
__device__ __forceinline__ void bf4(float2 a, float2 b, float2 c, float2 d,
                                    float2& o0, float2& o1, float2& o2, float2& o3) {
    float2 apc = cadd(a, c), amc = csub(a, c);
    float2 bpd = cadd(b, d), bmd = csub(b, d);
    o0 = cadd(apc, bpd);
    o2 = csub(apc, bpd);
    if (FWD) {
        o1 = make_float2(amc.x + bmd.y, amc.y - bmd.x);
        o3 = make_float2(amc.x - bmd.y, amc.y + bmd.x);
    } else {
        o1 = make_float2(amc.x - bmd.y, amc.y + bmd.x);
        o3 = make_float2(amc.x + bmd.y, amc.y - bmd.x);
    }
}

template <bool FWD>
__device__ __forceinline__ void fft16(float2* z) {
    const float S  = FWD ? -1.f : 1.f;
    const float C1 = 0.92387953251128674f;
    const float S1 = 0.38268343236508977f;
    const float R  = 0.70710678118654752f;
    float2 A[16];
#pragma unroll
    for (int n1 = 0; n1 < 4; n1++)
        bf4<FWD>(z[n1], z[n1 + 4], z[n1 + 8], z[n1 + 12],
                 A[n1 * 4 + 0], A[n1 * 4 + 1], A[n1 * 4 + 2], A[n1 * 4 + 3]);
    A[5]  = cmul(A[5],  make_float2( C1,  S * S1));
    A[6]  = cmul(A[6],  make_float2( R,   S * R ));
    A[7]  = cmul(A[7],  make_float2( S1,  S * C1));
    A[9]  = cmul(A[9],  make_float2( R,   S * R ));
    A[10] = make_float2(-S * A[10].y, S * A[10].x);
    A[11] = cmul(A[11], make_float2(-R,   S * R ));
    A[13] = cmul(A[13], make_float2( S1,  S * C1));
    A[14] = cmul(A[14], make_float2(-R,   S * R ));
    A[15] = cmul(A[15], make_float2(-C1, -S * S1));
#pragma unroll
    for (int k2 = 0; k2 < 4; k2++)
        bf4<FWD>(A[k2], A[4 + k2], A[8 + k2], A[12 + k2],
                 z[k2], z[k2 + 4], z[k2 + 8], z[k2 + 12]);
}

// ---------------- forward stage 0 fused with (-1)^n pack AND global init ----------------
__global__ void __launch_bounds__(256) fwd0_kernel(const float* __restrict__ x,
                                                   const float* __restrict__ om0in) {
    if (blockIdx.x == 0 && threadIdx.x == 0) {
        g_om[0] = 0.5f * om0in[0]; g_om[1] = 0.5f * om0in[1]; g_om[2] = 0.5f * om0in[2];
#pragma unroll
        for (int s = 0; s < 4; s++)
#pragma unroll
            for (int i = 0; i < 8; i++) g_acc4.a[s][i] = 0.0;
        g_ctrB.c = 0u;
        g_goB.g = 0u;
    }
    int p = blockIdx.x * blockDim.x + threadIdx.x;
    float sgn = (p & 1) ? -1.f : 1.f;
    float2 z[16];
#pragma unroll
    for (int j = 0; j < 16; j++) z[j] = make_float2(sgn * x[p + j * 65536], 0.f);
    fft16<true>(z);
    float th0 = (float)(-2.0 * PI_D / (double)TN);
    float sn, cs;
    sincosf(th0 * (float)p, &sn, &cs);
    float2 w = make_float2(cs, sn), cur = w;
    int ob = p << 4;
    g_Bb[ob] = z[0];
#pragma unroll
    for (int r = 1; r < 16; r++) {
        g_Bb[ob + r] = cmul(z[r], cur);
        cur = cmul(cur, w);
    }
}

// ---------------- generic radix-16 Stockham stage (batched) ----------------
template <bool FWD>
__global__ void __launch_bounds__(256) fft16_stage(int inIsB, int log2s, float th0) {
    int gid  = blockIdx.x * blockDim.x + threadIdx.x;
    int tid  = gid & 65535;
    int base = (gid >> 16) << LOG2TN;
    const float2* __restrict__ X = (inIsB ? g_Bb : g_A) + base;
    float2* __restrict__       Y = (inIsB ? g_A : g_Bb) + base;
    int s_ = 1 << log2s;
    int q  = tid & (s_ - 1);
    int p  = tid >> log2s;
    int m  = TN >> (log2s + 4);

    float2 z[16];
#pragma unroll
    for (int j = 0; j < 16; j++) z[j] = X[q + ((p + j * m) << log2s)];
    fft16<FWD>(z);
    float sn, cs;
    sincosf(th0 * (float)p, &sn, &cs);
    float2 w = make_float2(cs, sn), cur = w;
    int ob = q + ((p << 4) << log2s);
    Y[ob] = z[0];
#pragma unroll
    for (int r = 1; r < 16; r++) {
        Y[ob + (r << log2s)] = cmul(z[r], cur);
        cur = cmul(cur, w);
    }
}

// ---------------- u + Hermitian pack + inverse stage 0 (fused, standalone) ----------------
__device__ __forceinline__ void eval_u(float fr, float2 fh, float2 la,
                                       float om0, float om1, float om2,
                                       float2& u0, float2& u1, float2& u2) {
    float d0 = fr - om0; d0 *= d0;
    float d1 = fr - om1; d1 *= d1;
    float d2 = fr - om2; d2 *= d2;
    float g0 = frcp(fmaf(C_ALPHA, (d0 + C_TAU2) + d1, 1.0f));
    float g1 = frcp(fmaf(C_ALPHA, ((d1 + C_TAU2) + d0) + d2, 1.0f));
    float g2 = frcp(fmaf(C_ALPHA, (d2 + C_TAU2) + d1, 1.0f));
    float G  = (g0 + g1) + g2;
    float inv = frcp(1.0f - 0.5f * C_TAU * G);
    float lox = (la.x - C_TAU * fh.x * (G - 1.0f)) * inv;
    float loy = (la.y - C_TAU * fh.y * (G - 1.0f)) * inv;
    float nr = fmaf(-0.5f, lox, fh.x);
    float ni = fmaf(-0.5f, loy, fh.y);
    u0 = make_float2(nr * g0, ni * g0);
    u1 = make_float2(nr * g1, ni * g1);
    u2 = make_float2(nr * g2, ni * g2);
}

__global__ void __launch_bounds__(256) ustage0_kernel() {
    int gid = blockIdx.x * blockDim.x + threadIdx.x;   // 0..65535
    float om0 = g_om[0], om1 = g_om[1], om2 = g_om[2];
    const float FRC = 1.0f / 1048576.0f;
    float frBase = fmaf((float)gid, FRC, -0.5f);
    int gm = (65536 - gid) & 65535;
    float frmBase = fmaf((float)gm, FRC, -0.5f);

    float2 P[16], Q[16];
#pragma unroll
    for (int j = 0; j < 16; j++) {
        int t  = j * 65536 + gid;
        int jm = (gid == 0) ? ((16 - j) & 15) : (15 - j);
        int tm = jm * 65536 + gm;
        float fr  = frBase + (float)j * 0.0625f;
        float frm = frmBase + (float)jm * 0.0625f;
        float2 u0, u1, u2, v0, v1, v2;
        eval_u(fr,  g_Bb[t],  g_lamPrev[t],  om0, om1, om2, u0, u1, u2);
        eval_u(frm, g_Bb[tm], g_lamPrev[tm], om0, om1, om2, v0, v1, v2);
        float h0x = 0.5f * (u0.x + v0.x), h0y = 0.5f * (u0.y - v0.y);
        float h1x = 0.5f * (u1.x + v1.x), h1y = 0.5f * (u1.y - v1.y);
        P[j] = make_float2(h0x - h1y, h0y + h1x);
        Q[j] = make_float2(0.5f * (u2.x + v2.x), 0.5f * (u2.y - v2.y));
    }

    float th0 = (float)(2.0 * PI_D / (double)TN);
    float sn, cs;
    sincosf(th0 * (float)gid, &sn, &cs);
    float2 w = make_float2(cs, sn);
    int ob = gid << 4;

    fft16<false>(P);
    {
        float2 cur = w;
        g_A[ob] = P[0];
#pragma unroll
        for (int r = 1; r < 16; r++) { g_A[ob + r] = cmul(P[r], cur); cur = cmul(cur, w); }
    }
    fft16<false>(Q);
    {
        float2 cur = w;
        g_A[TN + ob] = Q[0];
#pragma unroll
        for (int r = 1; r < 16; r++) { g_A[TN + ob + r] = cmul(Q[r], cur); cur = cmul(cur, w); }
    }
}

// ---------------- final inverse stage fused with real output (reads g_Bb) ----------------
__global__ void __launch_bounds__(256) inv_final_kernel(float* __restrict__ out) {
    int gid = blockIdx.x * blockDim.x + threadIdx.x;   // 0..131071
    int q = gid & 65535;
    int b = gid >> 16;
    const float2* __restrict__ X = g_Bb + (b << LOG2TN);
    float2 z[16];
#pragma unroll
    for (int j = 0; j < 16; j++) z[j] = X[q + (j << 16)];
    fft16<false>(z);
    float sg = (q & 1) ? -(1.0f / 1048576.0f) : (1.0f / 1048576.0f);
    if (b == 0) {
#pragma unroll
        for (int r = 0; r < 16; r++) {
            out[q + (r << 16)]      = z[r].x * sg;   // y0 = Re
            out[TN + q + (r << 16)] = z[r].y * sg;   // y1 = Im
        }
    } else {
#pragma unroll
        for (int r = 0; r < 16; r++)
            out[2 * TN + q + (r << 16)] = z[r].x * sg;  // y2 = Re
    }
}

// ---------------- persistent VMD iteration kernel (packed f32x2) ----------------
#define NBP 128
#define NTP 512
#define PJ 8      // 8 pairs = 16 elements per thread; NBP*NTP*16 = 2^20

__global__ void __launch_bounds__(NTP) vmd_persist() {
    int tid = threadIdx.x;
    int gid = blockIdx.x * NTP + tid;

    ull fhxP[PJ], fhyP[PJ], laxP[PJ], layP[PJ];
#pragma unroll
    for (int j = 0; j < PJ; j++) {
        float2 v0 = g_Bb[(2 * j) * 65536 + gid];
        float2 v1 = g_Bb[(2 * j + 1) * 65536 + gid];
        fhxP[j] = pk(v0.x, v1.x);
        fhyP[j] = pk(v0.y, v1.y);
        laxP[j] = 0ULL; layP[j] = 0ULL;
    }
    float om0 = g_om[0], om1 = g_om[1], om2 = g_om[2];
    float oD0 = om0, oD1 = om1, oD2 = om2;

    __shared__ float  sred[8][NTP / 32];
    __shared__ double sPrev[8];
    __shared__ float  sOm[3];
    __shared__ int    sTerm;
    if (tid < 8) sPrev[tid] = 0.0;
    __syncthreads();

    const float FRC = 1.0f / 1048576.0f;
    float frBase = fmaf((float)gid, FRC, -0.5f);

    const ull T2P   = pk(C_TAU2, C_TAU2);
    const ull ONEP  = pk(1.0f, 1.0f);
    const ull ALP   = pk(C_ALPHA, C_ALPHA);
    const ull NHALF = pk(-0.5f, -0.5f);
    const ull TAUP  = pk(C_TAU, C_TAU);
    const ull NTAUP = pk(-C_TAU, -C_TAU);
    const ull C1P   = pk(1.0f - 0.5f * C_TAU, 1.0f - 0.5f * C_TAU);

    const int slot = blockIdx.x & 3;

    for (int n = 0; n < 50; n++) {
        ull a0 = 0ULL, a1 = 0ULL, a2 = 0ULL, a3 = 0ULL, a4 = 0ULL, a5 = 0ULL;
        float a6 = 0.f, a7 = 0.f;

        // ---- rare paths hoisted OUT of the hot loop (use lambda ENTERING this iteration) ----
        if ((n > 0) && (n % 10 == 0)) {           // convergence diff
#pragma unroll 4
            for (int e = 0; e < 16; e++) {
                float fr = frBase + (float)e * 0.0625f;
                float lax, lay;
                { float lo, hi; upk(lo, hi, laxP[e >> 1]); lax = (e & 1) ? hi : lo; }
                { float lo, hi; upk(lo, hi, layP[e >> 1]); lay = (e & 1) ? hi : lo; }
                float cfx, cfy;
                { float lo, hi; upk(lo, hi, fhxP[e >> 1]); cfx = (e & 1) ? hi : lo; }
                { float lo, hi; upk(lo, hi, fhyP[e >> 1]); cfy = (e & 1) ? hi : lo; }
                float d0 = fr - om0; d0 *= d0;
                float d1 = fr - om1; d1 *= d1;
                float d2 = fr - om2; d2 *= d2;
                float cg0 = frcp(fmaf(C_ALPHA, (d0 + C_TAU2) + d1, 1.0f));
                float cg1 = frcp(fmaf(C_ALPHA, ((d1 + C_TAU2) + d0) + d2, 1.0f));
                float cg2 = frcp(fmaf(C_ALPHA, (d2 + C_TAU2) + d1, 1.0f));
                float cnr = fmaf(-0.5f, lax, cfx);
                float cni = fmaf(-0.5f, lay, cfy);
                float2 lp = g_lamPrev[e * 65536 + gid];
                float q0 = fr - oD0; q0 *= q0;
                float q1 = fr - oD1; q1 *= q1;
                float q2 = fr - oD2; q2 *= q2;
                float h0 = frcp(fmaf(C_ALPHA, (q0 + C_TAU2) + q1, 1.0f));
                float h1 = frcp(fmaf(C_ALPHA, ((q1 + C_TAU2) + q0) + q2, 1.0f));
                float h2 = frcp(fmaf(C_ALPHA, (q2 + C_TAU2) + q1, 1.0f));
                float mr = fmaf(-0.5f, lp.x, cfx);
                float mi = fmaf(-0.5f, lp.y, cfy);
                float ex0 = cnr * cg0 - mr * h0, ey0 = cni * cg0 - mi * h0;
                float ex1 = cnr * cg1 - mr * h1, ey1 = cni * cg1 - mi * h1;
                float ex2 = cnr * cg2 - mr * h2, ey2 = cni * cg2 - mi * h2;
                a6 += ex0 * ex0 + ey0 * ey0 + ex1 * ex1 + ey1 * ey1 + ex2 * ex2 + ey2 * ey2;
                a7 += (mr * mr + mi * mi) * (h0 * h0 + h1 * h1 + h2 * h2);
            }
        }
        if ((n % 10 == 9) && (n < 49)) {          // stash lambda entering this iteration
#pragma unroll
            for (int j = 0; j < PJ; j++) {
                float lxl, lxh, lyl, lyh;
                upk(lxl, lxh, laxP[j]); upk(lyl, lyh, layP[j]);
                g_lamPrev[(2 * j) * 65536 + gid]     = make_float2(lxl, lyl);
                g_lamPrev[(2 * j + 1) * 65536 + gid] = make_float2(lxh, lyh);
            }
        }

        ull NOM0 = pk(-om0, -om0), NOM1 = pk(-om1, -om1), NOM2 = pk(-om2, -om2);

        // ---- hot loop: pure packed arithmetic ----
#pragma unroll
        for (int j = 0; j < PJ; j++) {
            float fr0 = frBase + (float)(2 * j) * 0.0625f;
            float fr1 = fr0 + 0.0625f;
            ull frP = pk(fr0, fr1);

            ull t0 = add2(frP, NOM0); ull d0 = mul2(t0, t0);
            ull t1 = add2(frP, NOM1); ull d1 = mul2(t1, t1);
            ull t2 = add2(frP, NOM2); ull d2 = mul2(t2, t2);
            ull e0 = add2(add2(d0, d1), T2P);
            ull e1 = add2(e0, d2);
            ull e2 = add2(add2(d1, d2), T2P);
            ull g0 = rcp2(fma2(ALP, e0, ONEP));
            ull g1 = rcp2(fma2(ALP, e1, ONEP));
            ull g2 = rcp2(fma2(ALP, e2, ONEP));

            ull nr = fma2(NHALF, laxP[j], fhxP[j]);
            ull ni = fma2(NHALF, layP[j], fhyP[j]);
            ull m2 = fma2(ni, ni, mul2(nr, nr));

            ull p0 = mul2(m2, mul2(g0, g0));
            ull p1 = mul2(m2, mul2(g1, g1));
            ull p2 = mul2(m2, mul2(g2, g2));
            a0 = add2(a0, p0); a1 = add2(a1, p1); a2 = add2(a2, p2);
            a3 = fma2(p0, frP, a3); a4 = fma2(p1, frP, a4); a5 = fma2(p2, frP, a5);

            ull G   = add2(add2(g0, g1), g2);
            ull tG1 = fma2(TAUP, G, NTAUP);          // tau*(G-1)
            laxP[j] = fma2(nr, tG1, mul2(laxP[j], C1P));
            layP[j] = fma2(ni, tG1, mul2(layP[j], C1P));
        }

        // ---- unpack packed accumulators, block reduce 8 scalars ----
        float vals[8];
        {
            float lo, hi;
            upk(lo, hi, a0); vals[0] = lo + hi;
            upk(lo, hi, a1); vals[1] = lo + hi;
            upk(lo, hi, a2); vals[2] = lo + hi;
            upk(lo, hi, a3); vals[3] = lo + hi;
            upk(lo, hi, a4); vals[4] = lo + hi;
            upk(lo, hi, a5); vals[5] = lo + hi;
            vals[6] = a6; vals[7] = a7;
        }
#pragma unroll
        for (int i = 0; i < 8; i++) {
            float v = vals[i];
#pragma unroll
            for (int o = 16; o > 0; o >>= 1) v += __shfl_down_sync(0xffffffffu, v, o);
            vals[i] = v;
        }
        int wid = tid >> 5, lid = tid & 31;
        if (lid == 0) {
#pragma unroll
            for (int i = 0; i < 8; i++) sred[i][wid] = vals[i];
        }
        __syncthreads();
        if (tid < 8) {
            double s = 0.0;
#pragma unroll
            for (int w = 0; w < NTP / 32; w++) s += (double)sred[tid][w];
            atomicAdd(&g_acc4.a[slot][tid], s);    // 4-way split: 32-deep per address
            __threadfence();
        }
        __syncthreads();

        // ---- arrival; last arriver ONLY writes the release word; hybrid spin ----
        if (tid == 0) {
            unsigned old = atomicAdd(&g_ctrB.c, 1u);
            if (old == (unsigned)NBP * (unsigned)(n + 1) - 1u) {
                __threadfence();
                g_goB.g = (unsigned)(n + 1);
            }
            int sp = 0;
            while (g_goB.g < (unsigned)(n + 1)) { if (++sp > 2048) __nanosleep(64); }
            __threadfence();
            // redundant scalar update from split monotone totals (parallel loads)
            float it[8];
#pragma unroll
            for (int i = 0; i < 8; i++) {
                double T = *((const volatile double*)&g_acc4.a[0][i])
                         + *((const volatile double*)&g_acc4.a[1][i])
                         + *((const volatile double*)&g_acc4.a[2][i])
                         + *((const volatile double*)&g_acc4.a[3][i]);
                it[i] = (float)(T - sPrev[i]);
                sPrev[i] = T;
            }
            float on0 = it[3] / (it[0] + 1e-8f);
            float on1 = it[4] / (it[1] + 1e-8f);
            float on2 = it[5] / (it[2] + 1e-8f);
            float odiff = (fabsf(on0 - on2) + fabsf(on1 - on0) + fabsf(on2 - on1)) * (1.0f / 3.0f);
            float udiff = (n == 0) ? (it[0] + it[1] + it[2]) * 1e8f
                                   : it[6] / (it[7] + 1e-8f);
            int done = (n % 10 == 0) && (udiff < 1e-6f) && (odiff < 1e-6f);
            sOm[0] = on0; sOm[1] = on1; sOm[2] = on2;
            sTerm = (done || n == 49) ? 1 : 0;
        }
        __syncthreads();

        if (sTerm) {
            // terminal: store raw lambda_new; ustage0_kernel does inversion + u + pack + stage 0
#pragma unroll
            for (int j = 0; j < PJ; j++) {
                float lxl, lxh, lyl, lyh;
                upk(lxl, lxh, laxP[j]); upk(lyl, lyh, layP[j]);
                g_lamPrev[(2 * j) * 65536 + gid]     = make_float2(lxl, lyl);
                g_lamPrev[(2 * j + 1) * 65536 + gid] = make_float2(lxh, lyh);
            }
            if (gid == 0) { g_om[0] = om0; g_om[1] = om1; g_om[2] = om2; }
            break;
        }
        oD0 = om0; oD1 = om1; oD2 = om2;
        om0 = sOm[0]; om1 = sOm[1]; om2 = sOm[2];
        __syncthreads();
    }
}

// ---------------- launch ----------------
extern "C" void kernel_launch(void* const* d_in, const int* in_sizes, int n_in,
                              void* d_out, int out_size) {
    const float* x   = (const float*)d_in[0];
    const float* om0 = (const float*)d_in[1];
    float* out = (float*)d_out;

    // forward FFT of (-1)^n x (stage 0 carries global init)
    fwd0_kernel<<<256, 256>>>(x, om0);
    for (int i = 1; i < 5; i++) {
        float th0 = (float)(-2.0 * PI_D * (double)(1 << (4 * i)) / (double)TN);
        fft16_stage<true><<<256, 256>>>(i & 1, 4 * i, th0);
    }

    vmd_persist<<<NBP, NTP>>>();      // ends by storing final lambda + omega

    ustage0_kernel<<<256, 256>>>();   // lambda -> u -> Hermitian pack (2 batches) + stage 0 -> g_A

    // inverse stages 1..3 (2 batches): A->B->A->B
    for (int i = 1; i < 4; i++) {
        float th0 = (float)(2.0 * PI_D * (double)(1 << (4 * i)) / (double)TN);
        fft16_stage<false><<<512, 256>>>(1 - (i & 1), 4 * i, th0);
    }
    // final stage fused with real output: batch0 -> y0 (Re), y1 (Im); batch1 -> y2 (Re)
    inv_final_kernel<<<512, 256>>>(out);
}

// round 12
// speedup vs baseline: 1.1957x; 1.1957x over previous
#include <cuda_runtime.h>

#define TN (1 << 20)
#define LOG2TN 20
#define KM 3
#define C_ALPHA 2000.0f
#define C_TAU 1e-7f
#define C_TAU2 1e-14f
#define PI_D 3.14159265358979323846

typedef unsigned long long ull;

// ---------------- scratch (device globals; no allocation allowed) ----------------
__device__ float2 g_A[2 * TN];        // FFT ping buffer (2 batches)
__device__ float2 g_Bb[2 * TN];       // FFT pong buffer; [0..TN) holds fhat after fwd
__device__ float2 g_lamPrev[TN];      // lambda stash / final lambda
struct __align__(128) AccBlk { double a[8]; double pad[8]; };
__device__ AccBlk g_accB;             // monotone accumulators (own line)
struct __align__(128) CtrBlk { unsigned c; unsigned pad[31]; };
__device__ CtrBlk g_ctrB;             // arrival counter (own line)
struct __align__(128) GoBlk { volatile unsigned g; unsigned pad[31]; };
__device__ GoBlk g_goB;               // release word (own line)
__device__ float g_om[KM];

__device__ __forceinline__ float frcp(float x) {
    float r; asm("rcp.approx.f32 %0, %1;" : "=f"(r) : "f"(x)); return r;
}

// ---------------- packed f32x2 helpers ----------------
__device__ __forceinline__ ull pk(float lo, float hi) {
    ull r; asm("mov.b64 %0, {%1, %2};" : "=l"(r) : "f"(lo), "f"(hi)); return r;
}
__device__ __forceinline__ void upk(float& lo, float& hi, ull v) {
    asm("mov.b64 {%0, %1}, %2;" : "=f"(lo), "=f"(hi) : "l"(v));
}
__device__ __forceinline__ ull fma2(ull a, ull b, ull c) {
    ull d; asm("fma.rn.f32x2 %0, %1, %2, %3;" : "=l"(d) : "l"(a), "l"(b), "l"(c)); return d;
}
__device__ __forceinline__ ull add2(ull a, ull b) {
    ull d; asm("add.rn.f32x2 %0, %1, %2;" : "=l"(d) : "l"(a), "l"(b)); return d;
}
__device__ __forceinline__ ull mul2(ull a, ull b) {
    ull d; asm("mul.rn.f32x2 %0, %1, %2;" : "=l"(d) : "l"(a), "l"(b)); return d;
}
__device__ __forceinline__ ull rcp2(ull a) {
    float lo, hi; upk(lo, hi, a); return pk(frcp(lo), frcp(hi));
}

// ---------------- complex helpers ----------------
__device__ __forceinline__ float2 cadd(float2 a, float2 b) { return make_float2(a.x + b.x, a.y + b.y); }
__device__ __forceinline__ float2 csub(float2 a, float2 b) { return make_float2(a.x - b.x, a.y - b.y); }
__device__ __forceinline__ float2 cmul(float2 a, float2 b) {
    return make_float2(a.x * b.x - a.y * b.y, a.x * b.y + a.y * b.x);
}

// twiddle powers W[1..15] from W1, binary tree (depth 4 instead of serial 15)
__device__ __forceinline__ void twiddle_powers(float2 W1, float2* W) {
    W[1] = W1;
    W[2]  = cmul(W1, W1);
    W[4]  = cmul(W[2], W[2]);
    W[8]  = cmul(W[4], W[4]);
    W[3]  = cmul(W[2], W1);
    W[5]  = cmul(W[4], W1);
    W[6]  = cmul(W[4], W[2]);
    W[7]  = cmul(W[4], W[3]);
    W[9]  = cmul(W[8], W1);
    W[10] = cmul(W[8], W[2]);
    W[11] = cmul(W[8], W[3]);
    W[12] = cmul(W[8], W[4]);
    W[13] = cmul(W[8], W[5]);
    W[14] = cmul(W[8], W[6]);
    W[15] = cmul(W[8], W[7]);
}

// ---------------- radix-16 butterfly ----------------
template <bool FWD>
__device__ __forceinline__ void bf4(float2 a, float2 b, float2 c, float2 d,
                                    float2& o0, float2& o1, float2& o2, float2& o3) {
    float2 apc = cadd(a, c), amc = csub(a, c);
    float2 bpd = cadd(b, d), bmd = csub(b, d);
    o0 = cadd(apc, bpd);
    o2 = csub(apc, bpd);
    if (FWD) {
        o1 = make_float2(amc.x + bmd.y, amc.y - bmd.x);
        o3 = make_float2(amc.x - bmd.y, amc.y + bmd.x);
    } else {
        o1 = make_float2(amc.x - bmd.y, amc.y + bmd.x);
        o3 = make_float2(amc.x + bmd.y, amc.y - bmd.x);
    }
}

template <bool FWD>
__device__ __forceinline__ void fft16(float2* z) {
    const float S  = FWD ? -1.f : 1.f;
    const float C1 = 0.92387953251128674f;
    const float S1 = 0.38268343236508977f;
    const float R  = 0.70710678118654752f;
    float2 A[16];
#pragma unroll
    for (int n1 = 0; n1 < 4; n1++)
        bf4<FWD>(z[n1], z[n1 + 4], z[n1 + 8], z[n1 + 12],
                 A[n1 * 4 + 0], A[n1 * 4 + 1], A[n1 * 4 + 2], A[n1 * 4 + 3]);
    A[5]  = cmul(A[5],  make_float2( C1,  S * S1));
    A[6]  = cmul(A[6],  make_float2( R,   S * R ));
    A[7]  = cmul(A[7],  make_float2( S1,  S * C1));
    A[9]  = cmul(A[9],  make_float2( R,   S * R ));
    A[10] = make_float2(-S * A[10].y, S * A[10].x);
    A[11] = cmul(A[11], make_float2(-R,   S * R ));
    A[13] = cmul(A[13], make_float2( S1,  S * C1));
    A[14] = cmul(A[14], make_float2(-R,   S * R ));
    A[15] = cmul(A[15], make_float2(-C1, -S * S1));
#pragma unroll
    for (int k2 = 0; k2 < 4; k2++)
        bf4<FWD>(A[k2], A[4 + k2], A[8 + k2], A[12 + k2],
                 z[k2], z[k2 + 4], z[k2 + 8], z[k2 + 12]);
}

// ---------------- forward stage 0 fused with (-1)^n pack AND global init ----------------
__global__ void __launch_bounds__(256) fwd0_kernel(const float* __restrict__ x,
                                                   const float* __restrict__ om0in) {
    if (blockIdx.x == 0 && threadIdx.x == 0) {
        g_om[0] = 0.5f * om0in[0]; g_om[1] = 0.5f * om0in[1]; g_om[2] = 0.5f * om0in[2];
#pragma unroll
        for (int i = 0; i < 8; i++) g_accB.a[i] = 0.0;
        g_ctrB.c = 0u;
        g_goB.g = 0u;
    }
    int p = blockIdx.x * blockDim.x + threadIdx.x;
    float sgn = (p & 1) ? -1.f : 1.f;
    float2 z[16];
#pragma unroll
    for (int j = 0; j < 16; j++) z[j] = make_float2(sgn * x[p + j * 65536], 0.f);
    fft16<true>(z);
    float th0 = (float)(-2.0 * PI_D / (double)TN);
    float sn, cs;
    __sincosf(th0 * (float)p, &sn, &cs);
    float2 W[16];
    twiddle_powers(make_float2(cs, sn), W);
    int ob = p << 4;
    g_Bb[ob] = z[0];
#pragma unroll
    for (int r = 1; r < 16; r++) g_Bb[ob + r] = cmul(z[r], W[r]);
}

// ---------------- generic radix-16 Stockham stage (batched) ----------------
template <bool FWD>
__global__ void __launch_bounds__(256) fft16_stage(int inIsB, int log2s, float th0) {
    int gid  = blockIdx.x * blockDim.x + threadIdx.x;
    int tid  = gid & 65535;
    int base = (gid >> 16) << LOG2TN;
    const float2* __restrict__ X = (inIsB ? g_Bb : g_A) + base;
    float2* __restrict__       Y = (inIsB ? g_A : g_Bb) + base;
    int s_ = 1 << log2s;
    int q  = tid & (s_ - 1);
    int p  = tid >> log2s;
    int m  = TN >> (log2s + 4);

    float2 z[16];
#pragma unroll
    for (int j = 0; j < 16; j++) z[j] = X[q + ((p + j * m) << log2s)];
    fft16<FWD>(z);
    float sn, cs;
    __sincosf(th0 * (float)p, &sn, &cs);
    float2 W[16];
    twiddle_powers(make_float2(cs, sn), W);
    int ob = q + ((p << 4) << log2s);
    Y[ob] = z[0];
#pragma unroll
    for (int r = 1; r < 16; r++) Y[ob + (r << log2s)] = cmul(z[r], W[r]);
}

// ---------------- u + Hermitian pack + inverse stage 0 (fused, standalone) ----------------
__device__ __forceinline__ void eval_u(float fr, float2 fh, float2 la,
                                       float om0, float om1, float om2,
                                       float2& u0, float2& u1, float2& u2) {
    float d0 = fr - om0; d0 *= d0;
    float d1 = fr - om1; d1 *= d1;
    float d2 = fr - om2; d2 *= d2;
    float g0 = frcp(fmaf(C_ALPHA, (d0 + C_TAU2) + d1, 1.0f));
    float g1 = frcp(fmaf(C_ALPHA, ((d1 + C_TAU2) + d0) + d2, 1.0f));
    float g2 = frcp(fmaf(C_ALPHA, (d2 + C_TAU2) + d1, 1.0f));
    float G  = (g0 + g1) + g2;
    float inv = frcp(1.0f - 0.5f * C_TAU * G);
    float lox = (la.x - C_TAU * fh.x * (G - 1.0f)) * inv;
    float loy = (la.y - C_TAU * fh.y * (G - 1.0f)) * inv;
    float nr = fmaf(-0.5f, lox, fh.x);
    float ni = fmaf(-0.5f, loy, fh.y);
    u0 = make_float2(nr * g0, ni * g0);
    u1 = make_float2(nr * g1, ni * g1);
    u2 = make_float2(nr * g2, ni * g2);
}

__global__ void __launch_bounds__(256) ustage0_kernel() {
    int gid = blockIdx.x * blockDim.x + threadIdx.x;   // 0..65535
    float om0 = g_om[0], om1 = g_om[1], om2 = g_om[2];
    const float FRC = 1.0f / 1048576.0f;
    float frBase = fmaf((float)gid, FRC, -0.5f);
    int gm = (65536 - gid) & 65535;
    float frmBase = fmaf((float)gm, FRC, -0.5f);

    float2 P[16], Q[16];
#pragma unroll
    for (int j = 0; j < 16; j++) {
        int t  = j * 65536 + gid;
        int jm = (gid == 0) ? ((16 - j) & 15) : (15 - j);
        int tm = jm * 65536 + gm;
        float fr  = frBase + (float)j * 0.0625f;
        float frm = frmBase + (float)jm * 0.0625f;
        float2 u0, u1, u2, v0, v1, v2;
        eval_u(fr,  g_Bb[t],  g_lamPrev[t],  om0, om1, om2, u0, u1, u2);
        eval_u(frm, g_Bb[tm], g_lamPrev[tm], om0, om1, om2, v0, v1, v2);
        float h0x = 0.5f * (u0.x + v0.x), h0y = 0.5f * (u0.y - v0.y);
        float h1x = 0.5f * (u1.x + v1.x), h1y = 0.5f * (u1.y - v1.y);
        P[j] = make_float2(h0x - h1y, h0y + h1x);
        Q[j] = make_float2(0.5f * (u2.x + v2.x), 0.5f * (u2.y - v2.y));
    }

    float th0 = (float)(2.0 * PI_D / (double)TN);
    float sn, cs;
    __sincosf(th0 * (float)gid, &sn, &cs);
    float2 W[16];
    twiddle_powers(make_float2(cs, sn), W);
    int ob = gid << 4;

    fft16<false>(P);
    g_A[ob] = P[0];
#pragma unroll
    for (int r = 1; r < 16; r++) g_A[ob + r] = cmul(P[r], W[r]);

    fft16<false>(Q);
    g_A[TN + ob] = Q[0];
#pragma unroll
    for (int r = 1; r < 16; r++) g_A[TN + ob + r] = cmul(Q[r], W[r]);
}

// ---------------- final inverse stage fused with real output (reads g_Bb) ----------------
__global__ void __launch_bounds__(256) inv_final_kernel(float* __restrict__ out) {
    int gid = blockIdx.x * blockDim.x + threadIdx.x;   // 0..131071
    int q = gid & 65535;
    int b = gid >> 16;
    const float2* __restrict__ X = g_Bb + (b << LOG2TN);
    float2 z[16];
#pragma unroll
    for (int j = 0; j < 16; j++) z[j] = X[q + (j << 16)];
    fft16<false>(z);
    float sg = (q & 1) ? -(1.0f / 1048576.0f) : (1.0f / 1048576.0f);
    if (b == 0) {
#pragma unroll
        for (int r = 0; r < 16; r++) {
            out[q + (r << 16)]      = z[r].x * sg;   // y0 = Re
            out[TN + q + (r << 16)] = z[r].y * sg;   // y1 = Im
        }
    } else {
#pragma unroll
        for (int r = 0; r < 16; r++)
            out[2 * TN + q + (r << 16)] = z[r].x * sg;  // y2 = Re
    }
}

// ---------------- persistent VMD iteration kernel (packed f32x2, R10-exact) ----------------
#define NBP 128
#define NTP 512
#define PJ 8      // 8 pairs = 16 elements per thread; NBP*NTP*16 = 2^20

__global__ void __launch_bounds__(NTP) vmd_persist() {
    int tid = threadIdx.x;
    int gid = blockIdx.x * NTP + tid;

    ull fhxP[PJ], fhyP[PJ], laxP[PJ], layP[PJ];
#pragma unroll
    for (int j = 0; j < PJ; j++) {
        float2 v0 = g_Bb[(2 * j) * 65536 + gid];
        float2 v1 = g_Bb[(2 * j + 1) * 65536 + gid];
        fhxP[j] = pk(v0.x, v1.x);
        fhyP[j] = pk(v0.y, v1.y);
        laxP[j] = 0ULL; layP[j] = 0ULL;
    }
    float om0 = g_om[0], om1 = g_om[1], om2 = g_om[2];
    float oD0 = om0, oD1 = om1, oD2 = om2;

    __shared__ float  sred[8][NTP / 32];
    __shared__ double sPrev[8];
    __shared__ float  sOm[3];
    __shared__ int    sTerm;
    if (tid < 8) sPrev[tid] = 0.0;
    __syncthreads();

    const float FRC = 1.0f / 1048576.0f;
    float frBase = fmaf((float)gid, FRC, -0.5f);

    const ull T2P   = pk(C_TAU2, C_TAU2);
    const ull ONEP  = pk(1.0f, 1.0f);
    const ull ALP   = pk(C_ALPHA, C_ALPHA);
    const ull NHALF = pk(-0.5f, -0.5f);
    const ull TAUP  = pk(C_TAU, C_TAU);
    const ull NTAUP = pk(-C_TAU, -C_TAU);
    const ull C1P   = pk(1.0f - 0.5f * C_TAU, 1.0f - 0.5f * C_TAU);

    for (int n = 0; n < 50; n++) {
        ull a0 = 0ULL, a1 = 0ULL, a2 = 0ULL, a3 = 0ULL, a4 = 0ULL, a5 = 0ULL;
        float a6 = 0.f, a7 = 0.f;
        bool doDiff  = (n > 0) && (n % 10 == 0);
        bool doStash = (n % 10 == 9) && (n < 49);

        ull NOM0 = pk(-om0, -om0), NOM1 = pk(-om1, -om1), NOM2 = pk(-om2, -om2);

#pragma unroll
        for (int j = 0; j < PJ; j++) {
            float fr0 = frBase + (float)(2 * j) * 0.0625f;
            float fr1 = fr0 + 0.0625f;
            ull frP = pk(fr0, fr1);

            ull t0 = add2(frP, NOM0); ull d0 = mul2(t0, t0);
            ull t1 = add2(frP, NOM1); ull d1 = mul2(t1, t1);
            ull t2 = add2(frP, NOM2); ull d2 = mul2(t2, t2);
            ull e0 = add2(add2(d0, d1), T2P);
            ull e1 = add2(e0, d2);
            ull e2 = add2(add2(d1, d2), T2P);
            ull g0 = rcp2(fma2(ALP, e0, ONEP));
            ull g1 = rcp2(fma2(ALP, e1, ONEP));
            ull g2 = rcp2(fma2(ALP, e2, ONEP));

            ull nr = fma2(NHALF, laxP[j], fhxP[j]);
            ull ni = fma2(NHALF, layP[j], fhyP[j]);
            ull m2 = fma2(ni, ni, mul2(nr, nr));

            ull p0 = mul2(m2, mul2(g0, g0));
            ull p1 = mul2(m2, mul2(g1, g1));
            ull p2 = mul2(m2, mul2(g2, g2));
            a0 = add2(a0, p0); a1 = add2(a1, p1); a2 = add2(a2, p2);
            a3 = fma2(p0, frP, a3); a4 = fma2(p1, frP, a4); a5 = fma2(p2, frP, a5);

            if (doDiff) {
                float nrl, nrh, nil, nih, g0l, g0h, g1l, g1h, g2l, g2h;
                upk(nrl, nrh, nr); upk(nil, nih, ni);
                upk(g0l, g0h, g0); upk(g1l, g1h, g1); upk(g2l, g2h, g2);
                float fhxl, fhxh, fhyl, fhyh;
                upk(fhxl, fhxh, fhxP[j]); upk(fhyl, fhyh, fhyP[j]);
#pragma unroll
                for (int s = 0; s < 2; s++) {
                    float fr  = s ? fr1 : fr0;
                    float cnr = s ? nrh : nrl, cni = s ? nih : nil;
                    float cg0 = s ? g0h : g0l, cg1 = s ? g1h : g1l, cg2 = s ? g2h : g2l;
                    float cfx = s ? fhxh : fhxl, cfy = s ? fhyh : fhyl;
                    float2 lp = g_lamPrev[(2 * j + s) * 65536 + gid];
                    float q0 = fr - oD0; q0 *= q0;
                    float q1 = fr - oD1; q1 *= q1;
                    float q2 = fr - oD2; q2 *= q2;
                    float h0 = frcp(fmaf(C_ALPHA, (q0 + C_TAU2) + q1, 1.0f));
                    float h1 = frcp(fmaf(C_ALPHA, ((q1 + C_TAU2) + q0) + q2, 1.0f));
                    float h2 = frcp(fmaf(C_ALPHA, (q2 + C_TAU2) + q1, 1.0f));
                    float mr = fmaf(-0.5f, lp.x, cfx);
                    float mi = fmaf(-0.5f, lp.y, cfy);
                    float ex0 = cnr * cg0 - mr * h0, ey0 = cni * cg0 - mi * h0;
                    float ex1 = cnr * cg1 - mr * h1, ey1 = cni * cg1 - mi * h1;
                    float ex2 = cnr * cg2 - mr * h2, ey2 = cni * cg2 - mi * h2;
                    a6 += ex0 * ex0 + ey0 * ey0 + ex1 * ex1 + ey1 * ey1 + ex2 * ex2 + ey2 * ey2;
                    a7 += (mr * mr + mi * mi) * (h0 * h0 + h1 * h1 + h2 * h2);
                }
            }
            if (doStash) {
                float lxl, lxh, lyl, lyh;
                upk(lxl, lxh, laxP[j]); upk(lyl, lyh, layP[j]);
                g_lamPrev[(2 * j) * 65536 + gid]     = make_float2(lxl, lyl);
                g_lamPrev[(2 * j + 1) * 65536 + gid] = make_float2(lxh, lyh);
            }

            ull G   = add2(add2(g0, g1), g2);
            ull tG1 = fma2(TAUP, G, NTAUP);          // tau*(G-1)
            laxP[j] = fma2(nr, tG1, mul2(laxP[j], C1P));
            layP[j] = fma2(ni, tG1, mul2(layP[j], C1P));
        }

        // ---- unpack packed accumulators, block reduce 8 scalars ----
        float vals[8];
        {
            float lo, hi;
            upk(lo, hi, a0); vals[0] = lo + hi;
            upk(lo, hi, a1); vals[1] = lo + hi;
            upk(lo, hi, a2); vals[2] = lo + hi;
            upk(lo, hi, a3); vals[3] = lo + hi;
            upk(lo, hi, a4); vals[4] = lo + hi;
            upk(lo, hi, a5); vals[5] = lo + hi;
            vals[6] = a6; vals[7] = a7;
        }
#pragma unroll
        for (int i = 0; i < 8; i++) {
            float v = vals[i];
#pragma unroll
            for (int o = 16; o > 0; o >>= 1) v += __shfl_down_sync(0xffffffffu, v, o);
            vals[i] = v;
        }
        int wid = tid >> 5, lid = tid & 31;
        if (lid == 0) {
#pragma unroll
            for (int i = 0; i < 8; i++) sred[i][wid] = vals[i];
        }
        __syncthreads();
        if (tid < 8) {
            double s = 0.0;
#pragma unroll
            for (int w = 0; w < NTP / 32; w++) s += (double)sred[tid][w];
            atomicAdd(&g_accB.a[tid], s);
            __threadfence();
        }
        __syncthreads();

        // ---- arrival; last arriver ONLY writes the release word; hybrid spin ----
        if (tid == 0) {
            unsigned old = atomicAdd(&g_ctrB.c, 1u);
            if (old == (unsigned)NBP * (unsigned)(n + 1) - 1u) {
                __threadfence();
                g_goB.g = (unsigned)(n + 1);
            }
            int sp = 0;
            while (g_goB.g < (unsigned)(n + 1)) { if (++sp > 2048) __nanosleep(64); }
            __threadfence();
            double T[8];
            float it[8];
#pragma unroll
            for (int i = 0; i < 8; i++) {
                T[i]  = *((const volatile double*)&g_accB.a[i]);
                it[i] = (float)(T[i] - sPrev[i]);
                sPrev[i] = T[i];
            }
            float on0 = it[3] / (it[0] + 1e-8f);
            float on1 = it[4] / (it[1] + 1e-8f);
            float on2 = it[5] / (it[2] + 1e-8f);
            float odiff = (fabsf(on0 - on2) + fabsf(on1 - on0) + fabsf(on2 - on1)) * (1.0f / 3.0f);
            float udiff = (n == 0) ? (it[0] + it[1] + it[2]) * 1e8f
                                   : it[6] / (it[7] + 1e-8f);
            int done = (n % 10 == 0) && (udiff < 1e-6f) && (odiff < 1e-6f);
            sOm[0] = on0; sOm[1] = on1; sOm[2] = on2;
            sTerm = (done || n == 49) ? 1 : 0;
        }
        __syncthreads();

        if (sTerm) {
#pragma unroll
            for (int j = 0; j < PJ; j++) {
                float lxl, lxh, lyl, lyh;
                upk(lxl, lxh, laxP[j]); upk(lyl, lyh, layP[j]);
                g_lamPrev[(2 * j) * 65536 + gid]     = make_float2(lxl, lyl);
                g_lamPrev[(2 * j + 1) * 65536 + gid] = make_float2(lxh, lyh);
            }
            if (gid == 0) { g_om[0] = om0; g_om[1] = om1; g_om[2] = om2; }
            break;
        }
        oD0 = om0; oD1 = om1; oD2 = om2;
        om0 = sOm[0]; om1 = sOm[1]; om2 = sOm[2];
        __syncthreads();
    }
}

// ---------------- launch ----------------
extern "C" void kernel_launch(void* const* d_in, const int* in_sizes, int n_in,
                              void* d_out, int out_size) {
    const float* x   = (const float*)d_in[0];
    const float* om0 = (const float*)d_in[1];
    float* out = (float*)d_out;

    // forward FFT of (-1)^n x (stage 0 carries global init)
    fwd0_kernel<<<256, 256>>>(x, om0);
    for (int i = 1; i < 5; i++) {
        float th0 = (float)(-2.0 * PI_D * (double)(1 << (4 * i)) / (double)TN);
        fft16_stage<true><<<256, 256>>>(i & 1, 4 * i, th0);
    }

    vmd_persist<<<NBP, NTP>>>();      // ends by storing final lambda + omega

    ustage0_kernel<<<256, 256>>>();   // lambda -> u -> Hermitian pack (2 batches) + stage 0 -> g_A

    // inverse stages 1..3 (2 batches): A->B->A->B
    for (int i = 1; i < 4; i++) {
        float th0 = (float)(2.0 * PI_D * (double)(1 << (4 * i)) / (double)TN);
        fft16_stage<false><<<512, 256>>>(1 - (i & 1), 4 * i, th0);
    }
    // final stage fused with real output: batch0 -> y0 (Re), y1 (Im); batch1 -> y2 (Re)
    inv_final_kernel<<<512, 256>>>(out);
}

// round 13
// speedup vs baseline: 1.2300x; 1.0287x over previous
#include <cuda_runtime.h>

#define TN (1 << 20)
#define LOG2TN 20
#define KM 3
#define C_ALPHA 2000.0f
#define C_TAU 1e-7f
#define C_TAU2 1e-14f
#define PI_D 3.14159265358979323846

typedef unsigned long long ull;

// ---------------- scratch (device globals; no allocation allowed) ----------------
__device__ float2 g_A[2 * TN];        // FFT ping buffer (2 batches)
__device__ float2 g_Bb[2 * TN];       // FFT pong buffer; [0..TN) holds fhat after fwd
__device__ float2 g_lamPrev[TN];      // lambda stash / final lambda
struct __align__(128) AccBlk { double a[8]; double pad[8]; };
__device__ AccBlk g_accB;             // monotone accumulators (own line)
struct __align__(128) CtrBlk { unsigned c; unsigned pad[31]; };
__device__ CtrBlk g_ctrB;             // arrival counter (own line)
struct __align__(128) GoBlk { volatile unsigned g; unsigned pad[31]; };
__device__ GoBlk g_goB;               // release word (own line)
__device__ float g_om[KM];

__device__ __forceinline__ float frcp(float x) {
    float r; asm("rcp.approx.f32 %0, %1;" : "=f"(r) : "f"(x)); return r;
}

// ---------------- packed f32x2 helpers ----------------
__device__ __forceinline__ ull pk(float lo, float hi) {
    ull r; asm("mov.b64 %0, {%1, %2};" : "=l"(r) : "f"(lo), "f"(hi)); return r;
}
__device__ __forceinline__ void upk(float& lo, float& hi, ull v) {
    asm("mov.b64 {%0, %1}, %2;" : "=f"(lo), "=f"(hi) : "l"(v));
}
__device__ __forceinline__ ull fma2(ull a, ull b, ull c) {
    ull d; asm("fma.rn.f32x2 %0, %1, %2, %3;" : "=l"(d) : "l"(a), "l"(b), "l"(c)); return d;
}
__device__ __forceinline__ ull add2(ull a, ull b) {
    ull d; asm("add.rn.f32x2 %0, %1, %2;" : "=l"(d) : "l"(a), "l"(b)); return d;
}
__device__ __forceinline__ ull mul2(ull a, ull b) {
    ull d; asm("mul.rn.f32x2 %0, %1, %2;" : "=l"(d) : "l"(a), "l"(b)); return d;
}
__device__ __forceinline__ ull rcp2(ull a) {
    float lo, hi; upk(lo, hi, a); return pk(frcp(lo), frcp(hi));
}

// ---------------- complex helpers ----------------
__device__ __forceinline__ float2 cadd(float2 a, float2 b) { return make_float2(a.x + b.x, a.y + b.y); }
__device__ __forceinline__ float2 csub(float2 a, float2 b) { return make_float2(a.x - b.x, a.y - b.y); }
__device__ __forceinline__ float2 cmul(float2 a, float2 b) {
    return make_float2(a.x * b.x - a.y * b.y, a.x * b.y + a.y * b.x);
}

// twiddle powers W[1..15] from W1, binary tree (depth 4)
__device__ __forceinline__ void twiddle_powers(float2 W1, float2* W) {
    W[1] = W1;
    W[2]  = cmul(W1, W1);
    W[4]  = cmul(W[2], W[2]);
    W[8]  = cmul(W[4], W[4]);
    W[3]  = cmul(W[2], W1);
    W[5]  = cmul(W[4], W1);
    W[6]  = cmul(W[4], W[2]);
    W[7]  = cmul(W[4], W[3]);
    W[9]  = cmul(W[8], W1);
    W[10] = cmul(W[8], W[2]);
    W[11] = cmul(W[8], W[3]);
    W[12] = cmul(W[8], W[4]);
    W[13] = cmul(W[8], W[5]);
    W[14] = cmul(W[8], W[6]);
    W[15] = cmul(W[8], W[7]);
}

// ---------------- radix-16 butterfly ----------------
template <bool FWD>
__device__ __forceinline__ void bf4(float2 a, float2 b, float2 c, float2 d,
                                    float2& o0, float2& o1, float2& o2, float2& o3) {
    float2 apc = cadd(a, c), amc = csub(a, c);
    float2 bpd = cadd(b, d), bmd = csub(b, d);
    o0 = cadd(apc, bpd);
    o2 = csub(apc, bpd);
    if (FWD) {
        o1 = make_float2(amc.x + bmd.y, amc.y - bmd.x);
        o3 = make_float2(amc.x - bmd.y, amc.y + bmd.x);
    } else {
        o1 = make_float2(amc.x - bmd.y, amc.y + bmd.x);
        o3 = make_float2(amc.x + bmd.y, amc.y - bmd.x);
    }
}

template <bool FWD>
__device__ __forceinline__ void fft16(float2* z) {
    const float S  = FWD ? -1.f : 1.f;
    const float C1 = 0.92387953251128674f;
    const float S1 = 0.38268343236508977f;
    const float R  = 0.70710678118654752f;
    float2 A[16];
#pragma unroll
    for (int n1 = 0; n1 < 4; n1++)
        bf4<FWD>(z[n1], z[n1 + 4], z[n1 + 8], z[n1 + 12],
                 A[n1 * 4 + 0], A[n1 * 4 + 1], A[n1 * 4 + 2], A[n1 * 4 + 3]);
    A[5]  = cmul(A[5],  make_float2( C1,  S * S1));
    A[6]  = cmul(A[6],  make_float2( R,   S * R ));
    A[7]  = cmul(A[7],  make_float2( S1,  S * C1));
    A[9]  = cmul(A[9],  make_float2( R,   S * R ));
    A[10] = make_float2(-S * A[10].y, S * A[10].x);
    A[11] = cmul(A[11], make_float2(-R,   S * R ));
    A[13] = cmul(A[13], make_float2( S1,  S * C1));
    A[14] = cmul(A[14], make_float2(-R,   S * R ));
    A[15] = cmul(A[15], make_float2(-C1, -S * S1));
#pragma unroll
    for (int k2 = 0; k2 < 4; k2++)
        bf4<FWD>(A[k2], A[4 + k2], A[8 + k2], A[12 + k2],
                 z[k2], z[k2 + 4], z[k2 + 8], z[k2 + 12]);
}

// ---------------- forward stage 0 fused with (-1)^n pack AND global init ----------------
__global__ void __launch_bounds__(256) fwd0_kernel(const float* __restrict__ x,
                                                   const float* __restrict__ om0in) {
    if (blockIdx.x == 0 && threadIdx.x == 0) {
        g_om[0] = 0.5f * om0in[0]; g_om[1] = 0.5f * om0in[1]; g_om[2] = 0.5f * om0in[2];
#pragma unroll
        for (int i = 0; i < 8; i++) g_accB.a[i] = 0.0;
        g_ctrB.c = 0u;
        g_goB.g = 0u;
    }
    int p = blockIdx.x * blockDim.x + threadIdx.x;
    float sgn = (p & 1) ? -1.f : 1.f;
    float2 z[16];
#pragma unroll
    for (int j = 0; j < 16; j++) z[j] = make_float2(sgn * x[p + j * 65536], 0.f);
    fft16<true>(z);
    float th0 = (float)(-2.0 * PI_D / (double)TN);
    float sn, cs;
    __sincosf(th0 * (float)p, &sn, &cs);
    float2 W[16];
    twiddle_powers(make_float2(cs, sn), W);
    int ob = p << 4;
    g_Bb[ob] = z[0];
#pragma unroll
    for (int r = 1; r < 16; r++) g_Bb[ob + r] = cmul(z[r], W[r]);
}

// ---------------- generic radix-16 Stockham stage (batched) ----------------
template <bool FWD>
__global__ void __launch_bounds__(256) fft16_stage(int inIsB, int log2s, float th0) {
    int gid  = blockIdx.x * blockDim.x + threadIdx.x;
    int tid  = gid & 65535;
    int base = (gid >> 16) << LOG2TN;
    const float2* __restrict__ X = (inIsB ? g_Bb : g_A) + base;
    float2* __restrict__       Y = (inIsB ? g_A : g_Bb) + base;
    int s_ = 1 << log2s;
    int q  = tid & (s_ - 1);
    int p  = tid >> log2s;
    int m  = TN >> (log2s + 4);

    float2 z[16];
#pragma unroll
    for (int j = 0; j < 16; j++) z[j] = X[q + ((p + j * m) << log2s)];
    fft16<FWD>(z);
    float sn, cs;
    __sincosf(th0 * (float)p, &sn, &cs);
    float2 W[16];
    twiddle_powers(make_float2(cs, sn), W);
    int ob = q + ((p << 4) << log2s);
    Y[ob] = z[0];
#pragma unroll
    for (int r = 1; r < 16; r++) Y[ob + (r << log2s)] = cmul(z[r], W[r]);
}

// ---------------- u + Hermitian pack + inverse stage 0 (fused, standalone) ----------------
__device__ __forceinline__ void eval_u(float fr, float2 fh, float2 la,
                                       float om0, float om1, float om2,
                                       float2& u0, float2& u1, float2& u2) {
    float d0 = fr - om0; d0 *= d0;
    float d1 = fr - om1; d1 *= d1;
    float d2 = fr - om2; d2 *= d2;
    float g0 = frcp(fmaf(C_ALPHA, (d0 + C_TAU2) + d1, 1.0f));
    float g1 = frcp(fmaf(C_ALPHA, ((d1 + C_TAU2) + d0) + d2, 1.0f));
    float g2 = frcp(fmaf(C_ALPHA, (d2 + C_TAU2) + d1, 1.0f));
    float G  = (g0 + g1) + g2;
    float inv = frcp(1.0f - 0.5f * C_TAU * G);
    float lox = (la.x - C_TAU * fh.x * (G - 1.0f)) * inv;
    float loy = (la.y - C_TAU * fh.y * (G - 1.0f)) * inv;
    float nr = fmaf(-0.5f, lox, fh.x);
    float ni = fmaf(-0.5f, loy, fh.y);
    u0 = make_float2(nr * g0, ni * g0);
    u1 = make_float2(nr * g1, ni * g1);
    u2 = make_float2(nr * g2, ni * g2);
}

__global__ void __launch_bounds__(256) ustage0_kernel() {
    int gid = blockIdx.x * blockDim.x + threadIdx.x;   // 0..65535
    float om0 = g_om[0], om1 = g_om[1], om2 = g_om[2];
    const float FRC = 1.0f / 1048576.0f;
    float frBase = fmaf((float)gid, FRC, -0.5f);
    int gm = (65536 - gid) & 65535;
    float frmBase = fmaf((float)gm, FRC, -0.5f);

    float2 P[16], Q[16];
#pragma unroll
    for (int j = 0; j < 16; j++) {
        int t  = j * 65536 + gid;
        int jm = (gid == 0) ? ((16 - j) & 15) : (15 - j);
        int tm = jm * 65536 + gm;
        float fr  = frBase + (float)j * 0.0625f;
        float frm = frmBase + (float)jm * 0.0625f;
        float2 u0, u1, u2, v0, v1, v2;
        eval_u(fr,  g_Bb[t],  g_lamPrev[t],  om0, om1, om2, u0, u1, u2);
        eval_u(frm, g_Bb[tm], g_lamPrev[tm], om0, om1, om2, v0, v1, v2);
        float h0x = 0.5f * (u0.x + v0.x), h0y = 0.5f * (u0.y - v0.y);
        float h1x = 0.5f * (u1.x + v1.x), h1y = 0.5f * (u1.y - v1.y);
        P[j] = make_float2(h0x - h1y, h0y + h1x);
        Q[j] = make_float2(0.5f * (u2.x + v2.x), 0.5f * (u2.y - v2.y));
    }

    float th0 = (float)(2.0 * PI_D / (double)TN);
    float sn, cs;
    __sincosf(th0 * (float)gid, &sn, &cs);
    float2 W[16];
    twiddle_powers(make_float2(cs, sn), W);
    int ob = gid << 4;

    fft16<false>(P);
    g_A[ob] = P[0];
#pragma unroll
    for (int r = 1; r < 16; r++) g_A[ob + r] = cmul(P[r], W[r]);

    fft16<false>(Q);
    g_A[TN + ob] = Q[0];
#pragma unroll
    for (int r = 1; r < 16; r++) g_A[TN + ob + r] = cmul(Q[r], W[r]);
}

// ---------------- final inverse stage fused with real output (reads g_Bb) ----------------
__global__ void __launch_bounds__(256) inv_final_kernel(float* __restrict__ out) {
    int gid = blockIdx.x * blockDim.x + threadIdx.x;   // 0..131071
    int q = gid & 65535;
    int b = gid >> 16;
    const float2* __restrict__ X = g_Bb + (b << LOG2TN);
    float2 z[16];
#pragma unroll
    for (int j = 0; j < 16; j++) z[j] = X[q + (j << 16)];
    fft16<false>(z);
    float sg = (q & 1) ? -(1.0f / 1048576.0f) : (1.0f / 1048576.0f);
    if (b == 0) {
#pragma unroll
        for (int r = 0; r < 16; r++) {
            out[q + (r << 16)]      = z[r].x * sg;   // y0 = Re
            out[TN + q + (r << 16)] = z[r].y * sg;   // y1 = Im
        }
    } else {
#pragma unroll
        for (int r = 0; r < 16; r++)
            out[2 * TN + q + (r << 16)] = z[r].x * sg;  // y2 = Re
    }
}

// ---------------- persistent VMD iteration kernel (packed f32x2) ----------------
#define NBP 128
#define NTP 512
#define PJ 8      // 8 pairs = 16 elements per thread; NBP*NTP*16 = 2^20

__global__ void __launch_bounds__(NTP) vmd_persist() {
    int tid = threadIdx.x;
    int gid = blockIdx.x * NTP + tid;

    ull fhxP[PJ], fhyP[PJ], laxP[PJ], layP[PJ];
#pragma unroll
    for (int j = 0; j < PJ; j++) {
        float2 v0 = g_Bb[(2 * j) * 65536 + gid];
        float2 v1 = g_Bb[(2 * j + 1) * 65536 + gid];
        fhxP[j] = pk(v0.x, v1.x);
        fhyP[j] = pk(v0.y, v1.y);
        laxP[j] = 0ULL; layP[j] = 0ULL;
    }
    float om0 = g_om[0], om1 = g_om[1], om2 = g_om[2];
    float oD0 = om0, oD1 = om1, oD2 = om2;

    __shared__ float  sred[8][NTP / 32];
    __shared__ double sPrev[8];
    __shared__ float  sOm[3];
    __shared__ int    sTerm;
    __shared__ int    sStashOK;
    if (tid < 8) sPrev[tid] = 0.0;
    if (tid == 0) sStashOK = 0;
    __syncthreads();

    const float FRC = 1.0f / 1048576.0f;
    float frBase = fmaf((float)gid, FRC, -0.5f);

    const ull T2P   = pk(C_TAU2, C_TAU2);
    const ull ONEP  = pk(1.0f, 1.0f);
    const ull ALP   = pk(C_ALPHA, C_ALPHA);
    const ull NHALF = pk(-0.5f, -0.5f);
    const ull TAUP  = pk(C_TAU, C_TAU);
    const ull NTAUP = pk(-C_TAU, -C_TAU);
    const ull C1P   = pk(1.0f - 0.5f * C_TAU, 1.0f - 0.5f * C_TAU);

    int stashedPrev = 0;   // uniform across all threads/blocks (derived from shared flag)

    for (int n = 0; n < 50; n++) {
        ull a0 = 0ULL, a1 = 0ULL, a2 = 0ULL, a3 = 0ULL, a4 = 0ULL, a5 = 0ULL;
        float a6 = 0.f, a7 = 0.f;
        // diff only if the stash at n-1 actually happened; stash only if modes are
        // close enough that `done` (odiff < 1e-6) could possibly fire at n+1.
        bool doDiff  = (n > 0) && (n % 10 == 0) && stashedPrev;
        bool doStash = (n % 10 == 9) && (n < 49) && (sStashOK != 0);

        ull NOM0 = pk(-om0, -om0), NOM1 = pk(-om1, -om1), NOM2 = pk(-om2, -om2);

#pragma unroll
        for (int j = 0; j < PJ; j++) {
            float fr0 = frBase + (float)(2 * j) * 0.0625f;
            float fr1 = fr0 + 0.0625f;
            ull frP = pk(fr0, fr1);

            ull t0 = add2(frP, NOM0); ull d0 = mul2(t0, t0);
            ull t1 = add2(frP, NOM1); ull d1 = mul2(t1, t1);
            ull t2 = add2(frP, NOM2); ull d2 = mul2(t2, t2);
            ull e0 = add2(add2(d0, d1), T2P);
            ull e1 = add2(e0, d2);
            ull e2 = add2(add2(d1, d2), T2P);
            ull g0 = rcp2(fma2(ALP, e0, ONEP));
            ull g1 = rcp2(fma2(ALP, e1, ONEP));
            ull g2 = rcp2(fma2(ALP, e2, ONEP));

            ull nr = fma2(NHALF, laxP[j], fhxP[j]);
            ull ni = fma2(NHALF, layP[j], fhyP[j]);
            ull m2 = fma2(ni, ni, mul2(nr, nr));

            ull p0 = mul2(m2, mul2(g0, g0));
            ull p1 = mul2(m2, mul2(g1, g1));
            ull p2 = mul2(m2, mul2(g2, g2));
            a0 = add2(a0, p0); a1 = add2(a1, p1); a2 = add2(a2, p2);
            a3 = fma2(p0, frP, a3); a4 = fma2(p1, frP, a4); a5 = fma2(p2, frP, a5);

            if (doDiff) {
                float nrl, nrh, nil, nih, g0l, g0h, g1l, g1h, g2l, g2h;
                upk(nrl, nrh, nr); upk(nil, nih, ni);
                upk(g0l, g0h, g0); upk(g1l, g1h, g1); upk(g2l, g2h, g2);
                float fhxl, fhxh, fhyl, fhyh;
                upk(fhxl, fhxh, fhxP[j]); upk(fhyl, fhyh, fhyP[j]);
#pragma unroll
                for (int s = 0; s < 2; s++) {
                    float fr  = s ? fr1 : fr0;
                    float cnr = s ? nrh : nrl, cni = s ? nih : nil;
                    float cg0 = s ? g0h : g0l, cg1 = s ? g1h : g1l, cg2 = s ? g2h : g2l;
                    float cfx = s ? fhxh : fhxl, cfy = s ? fhyh : fhyl;
                    float2 lp = g_lamPrev[(2 * j + s) * 65536 + gid];
                    float q0 = fr - oD0; q0 *= q0;
                    float q1 = fr - oD1; q1 *= q1;
                    float q2 = fr - oD2; q2 *= q2;
                    float h0 = frcp(fmaf(C_ALPHA, (q0 + C_TAU2) + q1, 1.0f));
                    float h1 = frcp(fmaf(C_ALPHA, ((q1 + C_TAU2) + q0) + q2, 1.0f));
                    float h2 = frcp(fmaf(C_ALPHA, (q2 + C_TAU2) + q1, 1.0f));
                    float mr = fmaf(-0.5f, lp.x, cfx);
                    float mi = fmaf(-0.5f, lp.y, cfy);
                    float ex0 = cnr * cg0 - mr * h0, ey0 = cni * cg0 - mi * h0;
                    float ex1 = cnr * cg1 - mr * h1, ey1 = cni * cg1 - mi * h1;
                    float ex2 = cnr * cg2 - mr * h2, ey2 = cni * cg2 - mi * h2;
                    a6 += ex0 * ex0 + ey0 * ey0 + ex1 * ex1 + ey1 * ey1 + ex2 * ex2 + ey2 * ey2;
                    a7 += (mr * mr + mi * mi) * (h0 * h0 + h1 * h1 + h2 * h2);
                }
            }
            if (doStash) {
                float lxl, lxh, lyl, lyh;
                upk(lxl, lxh, laxP[j]); upk(lyl, lyh, layP[j]);
                g_lamPrev[(2 * j) * 65536 + gid]     = make_float2(lxl, lyl);
                g_lamPrev[(2 * j + 1) * 65536 + gid] = make_float2(lxh, lyh);
            }

            ull G   = add2(add2(g0, g1), g2);
            ull tG1 = fma2(TAUP, G, NTAUP);          // tau*(G-1)
            laxP[j] = fma2(nr, tG1, mul2(laxP[j], C1P));
            layP[j] = fma2(ni, tG1, mul2(layP[j], C1P));
        }

        // ---- unpack packed accumulators, block reduce 8 scalars ----
        float vals[8];
        {
            float lo, hi;
            upk(lo, hi, a0); vals[0] = lo + hi;
            upk(lo, hi, a1); vals[1] = lo + hi;
            upk(lo, hi, a2); vals[2] = lo + hi;
            upk(lo, hi, a3); vals[3] = lo + hi;
            upk(lo, hi, a4); vals[4] = lo + hi;
            upk(lo, hi, a5); vals[5] = lo + hi;
            vals[6] = a6; vals[7] = a7;
        }
#pragma unroll
        for (int i = 0; i < 8; i++) {
            float v = vals[i];
#pragma unroll
            for (int o = 16; o > 0; o >>= 1) v += __shfl_down_sync(0xffffffffu, v, o);
            vals[i] = v;
        }
        int wid = tid >> 5, lid = tid & 31;
        if (lid == 0) {
#pragma unroll
            for (int i = 0; i < 8; i++) sred[i][wid] = vals[i];
        }
        __syncthreads();
        if (tid < 8) {
            double s = 0.0;
#pragma unroll
            for (int w = 0; w < NTP / 32; w++) s += (double)sred[tid][w];
            atomicAdd(&g_accB.a[tid], s);
            __threadfence();
        }
        __syncthreads();

        // ---- arrival; last arriver ONLY writes the release word; hybrid spin ----
        if (tid == 0) {
            unsigned old = atomicAdd(&g_ctrB.c, 1u);
            if (old == (unsigned)NBP * (unsigned)(n + 1) - 1u) {
                __threadfence();
                g_goB.g = (unsigned)(n + 1);
            }
            int sp = 0;
            while (g_goB.g < (unsigned)(n + 1)) { if (++sp > 2048) __nanosleep(64); }
            __threadfence();
            double T[8];
            float it[8];
#pragma unroll
            for (int i = 0; i < 8; i++) {
                T[i]  = *((const volatile double*)&g_accB.a[i]);
                it[i] = (float)(T[i] - sPrev[i]);
                sPrev[i] = T[i];
            }
            float on0 = it[3] / (it[0] + 1e-8f);
            float on1 = it[4] / (it[1] + 1e-8f);
            float on2 = it[5] / (it[2] + 1e-8f);
            float odiff = (fabsf(on0 - on2) + fabsf(on1 - on0) + fabsf(on2 - on1)) * (1.0f / 3.0f);
            float udiff;
            if (n == 0)            udiff = (it[0] + it[1] + it[2]) * 1e8f;
            else if (stashedPrev && (n % 10 == 0)) udiff = it[6] / (it[7] + 1e-8f);
            else                   udiff = 1e30f;   // diff skipped: odiff >= 1e-2 >> TOL anyway
            int done = (n % 10 == 0) && (udiff < 1e-6f) && (odiff < 1e-6f);
            sOm[0] = on0; sOm[1] = on1; sOm[2] = on2;
            sStashOK = (odiff < 1e-2f) ? 1 : 0;
            sTerm = (done || n == 49) ? 1 : 0;
        }
        __syncthreads();

        stashedPrev = doStash ? 1 : 0;

        if (sTerm) {
#pragma unroll
            for (int j = 0; j < PJ; j++) {
                float lxl, lxh, lyl, lyh;
                upk(lxl, lxh, laxP[j]); upk(lyl, lyh, layP[j]);
                g_lamPrev[(2 * j) * 65536 + gid]     = make_float2(lxl, lyl);
                g_lamPrev[(2 * j + 1) * 65536 + gid] = make_float2(lxh, lyh);
            }
            if (gid == 0) { g_om[0] = om0; g_om[1] = om1; g_om[2] = om2; }
            break;
        }
        oD0 = om0; oD1 = om1; oD2 = om2;
        om0 = sOm[0]; om1 = sOm[1]; om2 = sOm[2];
        __syncthreads();
    }
}

// ---------------- launch ----------------
extern "C" void kernel_launch(void* const* d_in, const int* in_sizes, int n_in,
                              void* d_out, int out_size) {
    const float* x   = (const float*)d_in[0];
    const float* om0 = (const float*)d_in[1];
    float* out = (float*)d_out;

    // forward FFT of (-1)^n x (stage 0 carries global init)
    fwd0_kernel<<<256, 256>>>(x, om0);
    for (int i = 1; i < 5; i++) {
        float th0 = (float)(-2.0 * PI_D * (double)(1 << (4 * i)) / (double)TN);
        fft16_stage<true><<<256, 256>>>(i & 1, 4 * i, th0);
    }

    vmd_persist<<<NBP, NTP>>>();      // ends by storing final lambda + omega

    ustage0_kernel<<<256, 256>>>();   // lambda -> u -> Hermitian pack (2 batches) + stage 0 -> g_A

    // inverse stages 1..3 (2 batches): A->B->A->B
    for (int i = 1; i < 4; i++) {
        float th0 = (float)(2.0 * PI_D * (double)(1 << (4 * i)) / (double)TN);
        fft16_stage<false><<<512, 256>>>(1 - (i & 1), 4 * i, th0);
    }
    // final stage fused with real output: batch0 -> y0 (Re), y1 (Im); batch1 -> y2 (Re)
    inv_final_kernel<<<512, 256>>>(out);
}

// round 14
// speedup vs baseline: 1.3795x; 1.1215x over previous
#include <cuda_runtime.h>

#define TN (1 << 20)
#define LOG2TN 20
#define KM 3
#define C_ALPHA 2000.0f
#define PI_D 3.14159265358979323846

typedef unsigned long long ull;

// ---------------- scratch (device globals; no allocation allowed) ----------------
__device__ float2 g_A[2 * TN];        // FFT ping buffer (2 batches)
__device__ float2 g_Bb[2 * TN];       // FFT pong buffer; [0..TN) holds fhat after fwd
struct __align__(128) AccBlk { double a[8]; double pad[8]; };
__device__ AccBlk g_accB;             // monotone accumulators (own line)
struct __align__(128) CtrBlk { unsigned c; unsigned pad[31]; };
__device__ CtrBlk g_ctrB;             // arrival counter (own line)
struct __align__(128) GoBlk { volatile unsigned g; unsigned pad[31]; };
__device__ GoBlk g_goB;               // release word (own line)
__device__ float g_om[KM];

__device__ __forceinline__ float frcp(float x) {
    float r; asm("rcp.approx.f32 %0, %1;" : "=f"(r) : "f"(x)); return r;
}

// ---------------- packed f32x2 helpers ----------------
__device__ __forceinline__ ull pk(float lo, float hi) {
    ull r; asm("mov.b64 %0, {%1, %2};" : "=l"(r) : "f"(lo), "f"(hi)); return r;
}
__device__ __forceinline__ void upk(float& lo, float& hi, ull v) {
    asm("mov.b64 {%0, %1}, %2;" : "=f"(lo), "=f"(hi) : "l"(v));
}
__device__ __forceinline__ ull fma2(ull a, ull b, ull c) {
    ull d; asm("fma.rn.f32x2 %0, %1, %2, %3;" : "=l"(d) : "l"(a), "l"(b), "l"(c)); return d;
}
__device__ __forceinline__ ull add2(ull a, ull b) {
    ull d; asm("add.rn.f32x2 %0, %1, %2;" : "=l"(d) : "l"(a), "l"(b)); return d;
}
__device__ __forceinline__ ull mul2(ull a, ull b) {
    ull d; asm("mul.rn.f32x2 %0, %1, %2;" : "=l"(d) : "l"(a), "l"(b)); return d;
}
__device__ __forceinline__ ull rcp2(ull a) {
    float lo, hi; upk(lo, hi, a); return pk(frcp(lo), frcp(hi));
}

// ---------------- complex helpers ----------------
__device__ __forceinline__ float2 cadd(float2 a, float2 b) { return make_float2(a.x + b.x, a.y + b.y); }
__device__ __forceinline__ float2 csub(float2 a, float2 b) { return make_float2(a.x - b.x, a.y - b.y); }
__device__ __forceinline__ float2 cmul(float2 a, float2 b) {
    return make_float2(a.x * b.x - a.y * b.y, a.x * b.y + a.y * b.x);
}

// twiddle powers W[1..15] from W1, binary tree (depth 4)
__device__ __forceinline__ void twiddle_powers(float2 W1, float2* W) {
    W[1] = W1;
    W[2]  = cmul(W1, W1);
    W[4]  = cmul(W[2], W[2]);
    W[8]  = cmul(W[4], W[4]);
    W[3]  = cmul(W[2], W1);
    W[5]  = cmul(W[4], W1);
    W[6]  = cmul(W[4], W[2]);
    W[7]  = cmul(W[4], W[3]);
    W[9]  = cmul(W[8], W1);
    W[10] = cmul(W[8], W[2]);
    W[11] = cmul(W[8], W[3]);
    W[12] = cmul(W[8], W[4]);
    W[13] = cmul(W[8], W[5]);
    W[14] = cmul(W[8], W[6]);
    W[15] = cmul(W[8], W[7]);
}

// ---------------- radix-16 butterfly ----------------
template <bool FWD>
__device__ __forceinline__ void bf4(float2 a, float2 b, float2 c, float2 d,
                                    float2& o0, float2& o1, float2& o2, float2& o3) {
    float2 apc = cadd(a, c), amc = csub(a, c);
    float2 bpd = cadd(b, d), bmd = csub(b, d);
    o0 = cadd(apc, bpd);
    o2 = csub(apc, bpd);
    if (FWD) {
        o1 = make_float2(amc.x + bmd.y, amc.y - bmd.x);
        o3 = make_float2(amc.x - bmd.y, amc.y + bmd.x);
    } else {
        o1 = make_float2(amc.x - bmd.y, amc.y + bmd.x);
        o3 = make_float2(amc.x + bmd.y, amc.y - bmd.x);
    }
}

template <bool FWD>
__device__ __forceinline__ void fft16(float2* z) {
    const float S  = FWD ? -1.f : 1.f;
    const float C1 = 0.92387953251128674f;
    const float S1 = 0.38268343236508977f;
    const float R  = 0.70710678118654752f;
    float2 A[16];
#pragma unroll
    for (int n1 = 0; n1 < 4; n1++)
        bf4<FWD>(z[n1], z[n1 + 4], z[n1 + 8], z[n1 + 12],
                 A[n1 * 4 + 0], A[n1 * 4 + 1], A[n1 * 4 + 2], A[n1 * 4 + 3]);
    A[5]  = cmul(A[5],  make_float2( C1,  S * S1));
    A[6]  = cmul(A[6],  make_float2( R,   S * R ));
    A[7]  = cmul(A[7],  make_float2( S1,  S * C1));
    A[9]  = cmul(A[9],  make_float2( R,   S * R ));
    A[10] = make_float2(-S * A[10].y, S * A[10].x);
    A[11] = cmul(A[11], make_float2(-R,   S * R ));
    A[13] = cmul(A[13], make_float2( S1,  S * C1));
    A[14] = cmul(A[14], make_float2(-R,   S * R ));
    A[15] = cmul(A[15], make_float2(-C1, -S * S1));
#pragma unroll
    for (int k2 = 0; k2 < 4; k2++)
        bf4<FWD>(A[k2], A[4 + k2], A[8 + k2], A[12 + k2],
                 z[k2], z[k2 + 4], z[k2 + 8], z[k2 + 12]);
}

// ---------------- forward stage 0 fused with (-1)^n pack AND global init ----------------
__global__ void __launch_bounds__(256) fwd0_kernel(const float* __restrict__ x,
                                                   const float* __restrict__ om0in) {
    if (blockIdx.x == 0 && threadIdx.x == 0) {
        g_om[0] = 0.5f * om0in[0]; g_om[1] = 0.5f * om0in[1]; g_om[2] = 0.5f * om0in[2];
#pragma unroll
        for (int i = 0; i < 8; i++) g_accB.a[i] = 0.0;
        g_ctrB.c = 0u;
        g_goB.g = 0u;
    }
    int p = blockIdx.x * blockDim.x + threadIdx.x;
    float sgn = (p & 1) ? -1.f : 1.f;
    float2 z[16];
#pragma unroll
    for (int j = 0; j < 16; j++) z[j] = make_float2(sgn * x[p + j * 65536], 0.f);
    fft16<true>(z);
    float th0 = (float)(-2.0 * PI_D / (double)TN);
    float sn, cs;
    __sincosf(th0 * (float)p, &sn, &cs);
    float2 W[16];
    twiddle_powers(make_float2(cs, sn), W);
    int ob = p << 4;
    g_Bb[ob] = z[0];
#pragma unroll
    for (int r = 1; r < 16; r++) g_Bb[ob + r] = cmul(z[r], W[r]);
}

// ---------------- generic radix-16 Stockham stage (batched) ----------------
template <bool FWD>
__global__ void __launch_bounds__(256) fft16_stage(int inIsB, int log2s, float th0) {
    int gid  = blockIdx.x * blockDim.x + threadIdx.x;
    int tid  = gid & 65535;
    int base = (gid >> 16) << LOG2TN;
    const float2* __restrict__ X = (inIsB ? g_Bb : g_A) + base;
    float2* __restrict__       Y = (inIsB ? g_A : g_Bb) + base;
    int s_ = 1 << log2s;
    int q  = tid & (s_ - 1);
    int p  = tid >> log2s;
    int m  = TN >> (log2s + 4);

    float2 z[16];
#pragma unroll
    for (int j = 0; j < 16; j++) z[j] = X[q + ((p + j * m) << log2s)];
    fft16<FWD>(z);
    float sn, cs;
    __sincosf(th0 * (float)p, &sn, &cs);
    float2 W[16];
    twiddle_powers(make_float2(cs, sn), W);
    int ob = q + ((p << 4) << log2s);
    Y[ob] = z[0];
#pragma unroll
    for (int r = 1; r < 16; r++) Y[ob + (r << log2s)] = cmul(z[r], W[r]);
}

// ---------------- u + Hermitian pack + inverse stage 0 (fused, standalone) ----------------
// u_k = fh * g_k  (lambda dropped: |lambda| ~ 5e-6 |fh|, below output tolerance)
__device__ __forceinline__ void eval_u(float fr, float2 fh,
                                       float om0, float om1, float om2,
                                       float2& u0, float2& u1, float2& u2) {
    float d0 = fr - om0; d0 *= d0;
    float d1 = fr - om1; d1 *= d1;
    float d2 = fr - om2; d2 *= d2;
    float g0 = frcp(fmaf(C_ALPHA, d0 + d1, 1.0f));
    float g1 = frcp(fmaf(C_ALPHA, (d1 + d0) + d2, 1.0f));
    float g2 = frcp(fmaf(C_ALPHA, d2 + d1, 1.0f));
    u0 = make_float2(fh.x * g0, fh.y * g0);
    u1 = make_float2(fh.x * g1, fh.y * g1);
    u2 = make_float2(fh.x * g2, fh.y * g2);
}

__global__ void __launch_bounds__(256) ustage0_kernel() {
    int gid = blockIdx.x * blockDim.x + threadIdx.x;   // 0..65535
    float om0 = g_om[0], om1 = g_om[1], om2 = g_om[2];
    const float FRC = 1.0f / 1048576.0f;
    float frBase = fmaf((float)gid, FRC, -0.5f);
    int gm = (65536 - gid) & 65535;
    float frmBase = fmaf((float)gm, FRC, -0.5f);

    float2 P[16], Q[16];
#pragma unroll
    for (int j = 0; j < 16; j++) {
        int t  = j * 65536 + gid;
        int jm = (gid == 0) ? ((16 - j) & 15) : (15 - j);
        int tm = jm * 65536 + gm;
        float fr  = frBase + (float)j * 0.0625f;
        float frm = frmBase + (float)jm * 0.0625f;
        float2 u0, u1, u2, v0, v1, v2;
        eval_u(fr,  g_Bb[t],  om0, om1, om2, u0, u1, u2);
        eval_u(frm, g_Bb[tm], om0, om1, om2, v0, v1, v2);
        float h0x = 0.5f * (u0.x + v0.x), h0y = 0.5f * (u0.y - v0.y);
        float h1x = 0.5f * (u1.x + v1.x), h1y = 0.5f * (u1.y - v1.y);
        P[j] = make_float2(h0x - h1y, h0y + h1x);
        Q[j] = make_float2(0.5f * (u2.x + v2.x), 0.5f * (u2.y - v2.y));
    }

    float th0 = (float)(2.0 * PI_D / (double)TN);
    float sn, cs;
    __sincosf(th0 * (float)gid, &sn, &cs);
    float2 W[16];
    twiddle_powers(make_float2(cs, sn), W);
    int ob = gid << 4;

    fft16<false>(P);
    g_A[ob] = P[0];
#pragma unroll
    for (int r = 1; r < 16; r++) g_A[ob + r] = cmul(P[r], W[r]);

    fft16<false>(Q);
    g_A[TN + ob] = Q[0];
#pragma unroll
    for (int r = 1; r < 16; r++) g_A[TN + ob + r] = cmul(Q[r], W[r]);
}

// ---------------- final inverse stage fused with real output (reads g_Bb) ----------------
__global__ void __launch_bounds__(256) inv_final_kernel(float* __restrict__ out) {
    int gid = blockIdx.x * blockDim.x + threadIdx.x;   // 0..131071
    int q = gid & 65535;
    int b = gid >> 16;
    const float2* __restrict__ X = g_Bb + (b << LOG2TN);
    float2 z[16];
#pragma unroll
    for (int j = 0; j < 16; j++) z[j] = X[q + (j << 16)];
    fft16<false>(z);
    float sg = (q & 1) ? -(1.0f / 1048576.0f) : (1.0f / 1048576.0f);
    if (b == 0) {
#pragma unroll
        for (int r = 0; r < 16; r++) {
            out[q + (r << 16)]      = z[r].x * sg;   // y0 = Re
            out[TN + q + (r << 16)] = z[r].y * sg;   // y1 = Im
        }
    } else {
#pragma unroll
        for (int r = 0; r < 16; r++)
            out[2 * TN + q + (r << 16)] = z[r].x * sg;  // y2 = Re
    }
}

// ---------------- persistent VMD iteration kernel (lambda-free, packed f32x2) ----------------
// State per thread: M2 = |fhat|^2 only (iteration-invariant). Per iteration:
// reduce sum(M2*g_k^2) and sum(M2*g_k^2*fr) over the grid, update omega.
#define NBP 128
#define NTP 512
#define PJ 8      // 8 pairs = 16 elements per thread; NBP*NTP*16 = 2^20

__global__ void __launch_bounds__(NTP) vmd_persist() {
    int tid = threadIdx.x;
    int gid = blockIdx.x * NTP + tid;

    ull M2P[PJ];
#pragma unroll
    for (int j = 0; j < PJ; j++) {
        float2 v0 = g_Bb[(2 * j) * 65536 + gid];
        float2 v1 = g_Bb[(2 * j + 1) * 65536 + gid];
        M2P[j] = pk(v0.x * v0.x + v0.y * v0.y, v1.x * v1.x + v1.y * v1.y);
    }
    float om0 = g_om[0], om1 = g_om[1], om2 = g_om[2];
    float oD0 = om0, oD1 = om1, oD2 = om2;

    __shared__ float  sred[8][NTP / 32];
    __shared__ double sPrev[8];
    __shared__ float  sOm[3];
    __shared__ int    sTerm;
    __shared__ int    sStashOK;
    if (tid < 8) sPrev[tid] = 0.0;
    if (tid == 0) sStashOK = 0;
    __syncthreads();

    const float FRC = 1.0f / 1048576.0f;
    float frBase = fmaf((float)gid, FRC, -0.5f);

    const ull ONEP = pk(1.0f, 1.0f);
    const ull ALP  = pk(C_ALPHA, C_ALPHA);

    int stashedPrev = 0;

    for (int n = 0; n < 50; n++) {
        ull a0 = 0ULL, a1 = 0ULL, a2 = 0ULL, a3 = 0ULL, a4 = 0ULL, a5 = 0ULL;
        float a6 = 0.f, a7 = 0.f;
        bool doDiff = (n > 0) && (n % 10 == 0) && stashedPrev;

        ull NOM0 = pk(-om0, -om0), NOM1 = pk(-om1, -om1), NOM2 = pk(-om2, -om2);

#pragma unroll
        for (int j = 0; j < PJ; j++) {
            float fr0 = frBase + (float)(2 * j) * 0.0625f;
            float fr1 = fr0 + 0.0625f;
            ull frP = pk(fr0, fr1);

            ull t0 = add2(frP, NOM0); ull d0 = mul2(t0, t0);
            ull t1 = add2(frP, NOM1); ull d1 = mul2(t1, t1);
            ull t2 = add2(frP, NOM2); ull d2 = mul2(t2, t2);
            ull e0 = add2(d0, d1);           // alpha*tau^2 = 2e-11 < fp32 eps of 1+..: dropped
            ull e1 = add2(e0, d2);
            ull e2 = add2(d1, d2);
            ull g0 = rcp2(fma2(ALP, e0, ONEP));
            ull g1 = rcp2(fma2(ALP, e1, ONEP));
            ull g2 = rcp2(fma2(ALP, e2, ONEP));

            ull p0 = mul2(M2P[j], mul2(g0, g0));
            ull p1 = mul2(M2P[j], mul2(g1, g1));
            ull p2 = mul2(M2P[j], mul2(g2, g2));
            a0 = add2(a0, p0); a1 = add2(a1, p1); a2 = add2(a2, p2);
            a3 = fma2(p0, frP, a3); a4 = fma2(p1, frP, a4); a5 = fma2(p2, frP, a5);

            if (doDiff) {
                // u_diff terms with u = fh*g: num += M2*sum_k (g_k - h_k)^2, den += M2*sum_k h_k^2
                float g0l, g0h, g1l, g1h, g2l, g2h, m2l, m2h;
                upk(g0l, g0h, g0); upk(g1l, g1h, g1); upk(g2l, g2h, g2);
                upk(m2l, m2h, M2P[j]);
#pragma unroll
                for (int s = 0; s < 2; s++) {
                    float fr  = s ? fr1 : fr0;
                    float cg0 = s ? g0h : g0l, cg1 = s ? g1h : g1l, cg2 = s ? g2h : g2l;
                    float cm2 = s ? m2h : m2l;
                    float q0 = fr - oD0; q0 *= q0;
                    float q1 = fr - oD1; q1 *= q1;
                    float q2 = fr - oD2; q2 *= q2;
                    float h0 = frcp(fmaf(C_ALPHA, q0 + q1, 1.0f));
                    float h1 = frcp(fmaf(C_ALPHA, (q1 + q0) + q2, 1.0f));
                    float h2 = frcp(fmaf(C_ALPHA, q2 + q1, 1.0f));
                    float e0s = cg0 - h0, e1s = cg1 - h1, e2s = cg2 - h2;
                    a6 += cm2 * (e0s * e0s + e1s * e1s + e2s * e2s);
                    a7 += cm2 * (h0 * h0 + h1 * h1 + h2 * h2);
                }
            }
        }

        // ---- unpack packed accumulators, block reduce 8 scalars ----
        float vals[8];
        {
            float lo, hi;
            upk(lo, hi, a0); vals[0] = lo + hi;
            upk(lo, hi, a1); vals[1] = lo + hi;
            upk(lo, hi, a2); vals[2] = lo + hi;
            upk(lo, hi, a3); vals[3] = lo + hi;
            upk(lo, hi, a4); vals[4] = lo + hi;
            upk(lo, hi, a5); vals[5] = lo + hi;
            vals[6] = a6; vals[7] = a7;
        }
#pragma unroll
        for (int i = 0; i < 8; i++) {
            float v = vals[i];
#pragma unroll
            for (int o = 16; o > 0; o >>= 1) v += __shfl_down_sync(0xffffffffu, v, o);
            vals[i] = v;
        }
        int wid = tid >> 5, lid = tid & 31;
        if (lid == 0) {
#pragma unroll
            for (int i = 0; i < 8; i++) sred[i][wid] = vals[i];
        }
        __syncthreads();
        if (tid < 8) {
            double s = 0.0;
#pragma unroll
            for (int w = 0; w < NTP / 32; w++) s += (double)sred[tid][w];
            atomicAdd(&g_accB.a[tid], s);
            __threadfence();
        }
        __syncthreads();

        // ---- arrival; last arriver ONLY writes the release word; hybrid spin ----
        if (tid == 0) {
            unsigned old = atomicAdd(&g_ctrB.c, 1u);
            if (old == (unsigned)NBP * (unsigned)(n + 1) - 1u) {
                __threadfence();
                g_goB.g = (unsigned)(n + 1);
            }
            int sp = 0;
            while (g_goB.g < (unsigned)(n + 1)) { if (++sp > 2048) __nanosleep(64); }
            __threadfence();
            double T[8];
            float it[8];
#pragma unroll
            for (int i = 0; i < 8; i++) {
                T[i]  = *((const volatile double*)&g_accB.a[i]);
                it[i] = (float)(T[i] - sPrev[i]);
                sPrev[i] = T[i];
            }
            float on0 = it[3] / (it[0] + 1e-8f);
            float on1 = it[4] / (it[1] + 1e-8f);
            float on2 = it[5] / (it[2] + 1e-8f);
            float odiff = (fabsf(on0 - on2) + fabsf(on1 - on0) + fabsf(on2 - on1)) * (1.0f / 3.0f);
            float udiff;
            if (n == 0)            udiff = (it[0] + it[1] + it[2]) * 1e8f;
            else if (stashedPrev && (n % 10 == 0)) udiff = it[6] / (it[7] + 1e-8f);
            else                   udiff = 1e30f;   // skipped: odiff >= 1e-2 >> TOL anyway
            int done = (n % 10 == 0) && (udiff < 1e-6f) && (odiff < 1e-6f);
            sOm[0] = on0; sOm[1] = on1; sOm[2] = on2;
            sStashOK = (odiff < 1e-2f) ? 1 : 0;
            sTerm = (done || n == 49) ? 1 : 0;
        }
        __syncthreads();

        // "stash" is now just remembering that omega history is valid for diff
        stashedPrev = ((n % 10 == 9) && (n < 49) && (sStashOK != 0)) ? 1 : 0;

        if (sTerm) {
            if (gid == 0) { g_om[0] = om0; g_om[1] = om1; g_om[2] = om2; }
            break;
        }
        oD0 = om0; oD1 = om1; oD2 = om2;
        om0 = sOm[0]; om1 = sOm[1]; om2 = sOm[2];
        __syncthreads();
    }
}

// ---------------- launch ----------------
extern "C" void kernel_launch(void* const* d_in, const int* in_sizes, int n_in,
                              void* d_out, int out_size) {
    const float* x   = (const float*)d_in[0];
    const float* om0 = (const float*)d_in[1];
    float* out = (float*)d_out;

    // forward FFT of (-1)^n x (stage 0 carries global init)
    fwd0_kernel<<<256, 256>>>(x, om0);
    for (int i = 1; i < 5; i++) {
        float th0 = (float)(-2.0 * PI_D * (double)(1 << (4 * i)) / (double)TN);
        fft16_stage<true><<<256, 256>>>(i & 1, 4 * i, th0);
    }

    vmd_persist<<<NBP, NTP>>>();      // ends by storing final omega

    ustage0_kernel<<<256, 256>>>();   // fhat -> u -> Hermitian pack (2 batches) + stage 0 -> g_A

    // inverse stages 1..3 (2 batches): A->B->A->B
    for (int i = 1; i < 4; i++) {
        float th0 = (float)(2.0 * PI_D * (double)(1 << (4 * i)) / (double)TN);
        fft16_stage<false><<<512, 256>>>(1 - (i & 1), 4 * i, th0);
    }
    // final stage fused with real output: batch0 -> y0 (Re), y1 (Im); batch1 -> y2 (Re)
    inv_final_kernel<<<512, 256>>>(out);
}

// round 15
// speedup vs baseline: 3.1799x; 2.3051x over previous
#include <cuda_runtime.h>

#define TN (1 << 20)
#define LOG2TN 20
#define KM 3
#define C_ALPHA 2000.0f
#define PI_D 3.14159265358979323846

typedef unsigned long long ull;

// ---------------- scratch (device globals; no allocation allowed) ----------------
__device__ float2 g_A[2 * TN];        // FFT ping buffer (2 batches)
__device__ float2 g_Bb[2 * TN];       // FFT pong buffer; [0..TN) holds fhat after fwd
#define NBIN 4096
__device__ float2 g_hist[NBIN];       // per-bin (S0 = sum M2, Sf = sum M2*fr)
__device__ float g_om[KM];

__device__ __forceinline__ float frcp(float x) {
    float r; asm("rcp.approx.f32 %0, %1;" : "=f"(r) : "f"(x)); return r;
}

// ---------------- complex helpers ----------------
__device__ __forceinline__ float2 cadd(float2 a, float2 b) { return make_float2(a.x + b.x, a.y + b.y); }
__device__ __forceinline__ float2 csub(float2 a, float2 b) { return make_float2(a.x - b.x, a.y - b.y); }
__device__ __forceinline__ float2 cmul(float2 a, float2 b) {
    return make_float2(a.x * b.x - a.y * b.y, a.x * b.y + a.y * b.x);
}

// twiddle powers W[1..15] from W1, binary tree (depth 4)
__device__ __forceinline__ void twiddle_powers(float2 W1, float2* W) {
    W[1] = W1;
    W[2]  = cmul(W1, W1);
    W[4]  = cmul(W[2], W[2]);
    W[8]  = cmul(W[4], W[4]);
    W[3]  = cmul(W[2], W1);
    W[5]  = cmul(W[4], W1);
    W[6]  = cmul(W[4], W[2]);
    W[7]  = cmul(W[4], W[3]);
    W[9]  = cmul(W[8], W1);
    W[10] = cmul(W[8], W[2]);
    W[11] = cmul(W[8], W[3]);
    W[12] = cmul(W[8], W[4]);
    W[13] = cmul(W[8], W[5]);
    W[14] = cmul(W[8], W[6]);
    W[15] = cmul(W[8], W[7]);
}

// ---------------- radix-16 butterfly ----------------
template <bool FWD>
__device__ __forceinline__ void bf4(float2 a, float2 b, float2 c, float2 d,
                                    float2& o0, float2& o1, float2& o2, float2& o3) {
    float2 apc = cadd(a, c), amc = csub(a, c);
    float2 bpd = cadd(b, d), bmd = csub(b, d);
    o0 = cadd(apc, bpd);
    o2 = csub(apc, bpd);
    if (FWD) {
        o1 = make_float2(amc.x + bmd.y, amc.y - bmd.x);
        o3 = make_float2(amc.x - bmd.y, amc.y + bmd.x);
    } else {
        o1 = make_float2(amc.x - bmd.y, amc.y + bmd.x);
        o3 = make_float2(amc.x + bmd.y, amc.y - bmd.x);
    }
}

template <bool FWD>
__device__ __forceinline__ void fft16(float2* z) {
    const float S  = FWD ? -1.f : 1.f;
    const float C1 = 0.92387953251128674f;
    const float S1 = 0.38268343236508977f;
    const float R  = 0.70710678118654752f;
    float2 A[16];
#pragma unroll
    for (int n1 = 0; n1 < 4; n1++)
        bf4<FWD>(z[n1], z[n1 + 4], z[n1 + 8], z[n1 + 12],
                 A[n1 * 4 + 0], A[n1 * 4 + 1], A[n1 * 4 + 2], A[n1 * 4 + 3]);
    A[5]  = cmul(A[5],  make_float2( C1,  S * S1));
    A[6]  = cmul(A[6],  make_float2( R,   S * R ));
    A[7]  = cmul(A[7],  make_float2( S1,  S * C1));
    A[9]  = cmul(A[9],  make_float2( R,   S * R ));
    A[10] = make_float2(-S * A[10].y, S * A[10].x);
    A[11] = cmul(A[11], make_float2(-R,   S * R ));
    A[13] = cmul(A[13], make_float2( S1,  S * C1));
    A[14] = cmul(A[14], make_float2(-R,   S * R ));
    A[15] = cmul(A[15], make_float2(-C1, -S * S1));
#pragma unroll
    for (int k2 = 0; k2 < 4; k2++)
        bf4<FWD>(A[k2], A[4 + k2], A[8 + k2], A[12 + k2],
                 z[k2], z[k2 + 4], z[k2 + 8], z[k2 + 12]);
}

// ---------------- forward stage 0 fused with (-1)^n pack AND global init ----------------
__global__ void __launch_bounds__(256) fwd0_kernel(const float* __restrict__ x,
                                                   const float* __restrict__ om0in) {
    if (blockIdx.x == 0 && threadIdx.x == 0) {
        g_om[0] = 0.5f * om0in[0]; g_om[1] = 0.5f * om0in[1]; g_om[2] = 0.5f * om0in[2];
    }
    int p = blockIdx.x * blockDim.x + threadIdx.x;
    float sgn = (p & 1) ? -1.f : 1.f;
    float2 z[16];
#pragma unroll
    for (int j = 0; j < 16; j++) z[j] = make_float2(sgn * x[p + j * 65536], 0.f);
    fft16<true>(z);
    float th0 = (float)(-2.0 * PI_D / (double)TN);
    float sn, cs;
    __sincosf(th0 * (float)p, &sn, &cs);
    float2 W[16];
    twiddle_powers(make_float2(cs, sn), W);
    int ob = p << 4;
    g_Bb[ob] = z[0];
#pragma unroll
    for (int r = 1; r < 16; r++) g_Bb[ob + r] = cmul(z[r], W[r]);
}

// ---------------- generic radix-16 Stockham stage (batched) ----------------
template <bool FWD>
__global__ void __launch_bounds__(256) fft16_stage(int inIsB, int log2s, float th0) {
    int gid  = blockIdx.x * blockDim.x + threadIdx.x;
    int tid  = gid & 65535;
    int base = (gid >> 16) << LOG2TN;
    const float2* __restrict__ X = (inIsB ? g_Bb : g_A) + base;
    float2* __restrict__       Y = (inIsB ? g_A : g_Bb) + base;
    int s_ = 1 << log2s;
    int q  = tid & (s_ - 1);
    int p  = tid >> log2s;
    int m  = TN >> (log2s + 4);

    float2 z[16];
#pragma unroll
    for (int j = 0; j < 16; j++) z[j] = X[q + ((p + j * m) << log2s)];
    fft16<FWD>(z);
    float sn, cs;
    __sincosf(th0 * (float)p, &sn, &cs);
    float2 W[16];
    twiddle_powers(make_float2(cs, sn), W);
    int ob = q + ((p << 4) << log2s);
    Y[ob] = z[0];
#pragma unroll
    for (int r = 1; r < 16; r++) Y[ob + (r << log2s)] = cmul(z[r], W[r]);
}

// ---------------- histogram: M2 weights onto NBIN bins (deterministic, warp/bin) ----------------
__global__ void __launch_bounds__(256) hist_kernel() {
    int warp = (blockIdx.x << 3) + (threadIdx.x >> 5);   // 512 blocks x 8 warps = 4096 bins
    int lane = threadIdx.x & 31;
    int base = warp << 8;                                 // 256 elements per bin
    const float FRC = 1.0f / 1048576.0f;
    float s0 = 0.f, sf = 0.f;
#pragma unroll
    for (int i = 0; i < 8; i++) {
        int t = base + lane + (i << 5);
        float2 v = g_Bb[t];
        float m2 = v.x * v.x + v.y * v.y;
        float fr = fmaf((float)t, FRC, -0.5f);
        s0 += m2;
        sf = fmaf(m2, fr, sf);
    }
#pragma unroll
    for (int o = 16; o; o >>= 1) {
        s0 += __shfl_down_sync(0xffffffffu, s0, o);
        sf += __shfl_down_sync(0xffffffffu, sf, o);
    }
    if (lane == 0) g_hist[warp] = make_float2(s0, sf);
}

// ---------------- 50 VMD iterations in ONE block over the histogram ----------------
#define ITPB 1024
#define PB (NBIN / ITPB)   // 4 bins per thread

__global__ void __launch_bounds__(ITPB) vmd_iter_kernel() {
    int tid = threadIdx.x;
    int wid = tid >> 5, lid = tid & 31;

    float S0[PB], Sf[PB], Fb[PB];
#pragma unroll
    for (int j = 0; j < PB; j++) {
        float2 h = g_hist[tid + j * ITPB];
        S0[j] = h.x; Sf[j] = h.y;
        Fb[j] = h.y * frcp(h.x + 1e-30f);    // M2-centroid of the bin
    }
    float om0 = g_om[0], om1 = g_om[1], om2 = g_om[2];
    float oD0 = om0, oD1 = om1, oD2 = om2;

    __shared__ float sred[8][ITPB / 32];
    __shared__ float sIt[8];
    __shared__ float sOm[3];
    __shared__ int   sTerm;
    __shared__ int   sStashOK;
    if (tid == 0) sStashOK = 0;
    __syncthreads();

    int stashedPrev = 0;

    for (int n = 0; n < 50; n++) {
        float a0 = 0.f, a1 = 0.f, a2 = 0.f, a3 = 0.f, a4 = 0.f, a5 = 0.f, a6 = 0.f, a7 = 0.f;
        bool doDiff = (n > 0) && (n % 10 == 0) && stashedPrev;

#pragma unroll
        for (int j = 0; j < PB; j++) {
            float f = Fb[j];
            float d0 = f - om0; d0 *= d0;
            float d1 = f - om1; d1 *= d1;
            float d2 = f - om2; d2 *= d2;
            float g0 = frcp(fmaf(C_ALPHA, d0 + d1, 1.0f));
            float g1 = frcp(fmaf(C_ALPHA, (d1 + d0) + d2, 1.0f));
            float g2 = frcp(fmaf(C_ALPHA, d2 + d1, 1.0f));
            float p0 = g0 * g0, p1 = g1 * g1, p2 = g2 * g2;
            a0 = fmaf(p0, S0[j], a0); a1 = fmaf(p1, S0[j], a1); a2 = fmaf(p2, S0[j], a2);
            a3 = fmaf(p0, Sf[j], a3); a4 = fmaf(p1, Sf[j], a4); a5 = fmaf(p2, Sf[j], a5);
            if (doDiff) {
                float q0 = f - oD0; q0 *= q0;
                float q1 = f - oD1; q1 *= q1;
                float q2 = f - oD2; q2 *= q2;
                float h0 = frcp(fmaf(C_ALPHA, q0 + q1, 1.0f));
                float h1 = frcp(fmaf(C_ALPHA, (q1 + q0) + q2, 1.0f));
                float h2 = frcp(fmaf(C_ALPHA, q2 + q1, 1.0f));
                float e0 = g0 - h0, e1 = g1 - h1, e2 = g2 - h2;
                a6 = fmaf(S0[j], e0 * e0 + e1 * e1 + e2 * e2, a6);
                a7 = fmaf(S0[j], h0 * h0 + h1 * h1 + h2 * h2, a7);
            }
        }

        // ---- block reduce 8 scalars over 32 warps ----
        float vals[8] = {a0, a1, a2, a3, a4, a5, a6, a7};
#pragma unroll
        for (int i = 0; i < 8; i++) {
            float v = vals[i];
#pragma unroll
            for (int o = 16; o > 0; o >>= 1) v += __shfl_down_sync(0xffffffffu, v, o);
            vals[i] = v;
        }
        if (lid == 0) {
#pragma unroll
            for (int i = 0; i < 8; i++) sred[i][wid] = vals[i];
        }
        __syncthreads();
        if (tid < 8) {
            float s = 0.f;
#pragma unroll
            for (int w = 0; w < ITPB / 32; w++) s += sred[tid][w];
            sIt[tid] = s;
        }
        __syncthreads();
        if (tid == 0) {
            float it0 = sIt[0], it1 = sIt[1], it2 = sIt[2];
            float on0 = sIt[3] / (it0 + 1e-8f);
            float on1 = sIt[4] / (it1 + 1e-8f);
            float on2 = sIt[5] / (it2 + 1e-8f);
            float odiff = (fabsf(on0 - on2) + fabsf(on1 - on0) + fabsf(on2 - on1)) * (1.0f / 3.0f);
            float udiff;
            if (n == 0)                              udiff = (it0 + it1 + it2) * 1e8f;
            else if (stashedPrev && (n % 10 == 0))   udiff = sIt[6] / (sIt[7] + 1e-8f);
            else                                     udiff = 1e30f;
            int done = (n % 10 == 0) && (udiff < 1e-6f) && (odiff < 1e-6f);
            sOm[0] = on0; sOm[1] = on1; sOm[2] = on2;
            sStashOK = (odiff < 1e-2f) ? 1 : 0;
            sTerm = (done || n == 49) ? 1 : 0;
        }
        __syncthreads();

        stashedPrev = ((n % 10 == 9) && (n < 49) && (sStashOK != 0)) ? 1 : 0;

        if (sTerm) {
            if (tid == 0) { g_om[0] = om0; g_om[1] = om1; g_om[2] = om2; }
            break;
        }
        oD0 = om0; oD1 = om1; oD2 = om2;
        om0 = sOm[0]; om1 = sOm[1]; om2 = sOm[2];
        __syncthreads();
    }
}

// ---------------- u + Hermitian pack + inverse stage 0 (fused, standalone) ----------------
// u_k = fh * g_k  (lambda dropped: |lambda| ~ 5e-6 |fh|, below output tolerance)
__device__ __forceinline__ void eval_u(float fr, float2 fh,
                                       float om0, float om1, float om2,
                                       float2& u0, float2& u1, float2& u2) {
    float d0 = fr - om0; d0 *= d0;
    float d1 = fr - om1; d1 *= d1;
    float d2 = fr - om2; d2 *= d2;
    float g0 = frcp(fmaf(C_ALPHA, d0 + d1, 1.0f));
    float g1 = frcp(fmaf(C_ALPHA, (d1 + d0) + d2, 1.0f));
    float g2 = frcp(fmaf(C_ALPHA, d2 + d1, 1.0f));
    u0 = make_float2(fh.x * g0, fh.y * g0);
    u1 = make_float2(fh.x * g1, fh.y * g1);
    u2 = make_float2(fh.x * g2, fh.y * g2);
}

__global__ void __launch_bounds__(256) ustage0_kernel() {
    int gid = blockIdx.x * blockDim.x + threadIdx.x;   // 0..65535
    float om0 = g_om[0], om1 = g_om[1], om2 = g_om[2];
    const float FRC = 1.0f / 1048576.0f;
    float frBase = fmaf((float)gid, FRC, -0.5f);
    int gm = (65536 - gid) & 65535;
    float frmBase = fmaf((float)gm, FRC, -0.5f);

    float2 P[16], Q[16];
#pragma unroll
    for (int j = 0; j < 16; j++) {
        int t  = j * 65536 + gid;
        int jm = (gid == 0) ? ((16 - j) & 15) : (15 - j);
        int tm = jm * 65536 + gm;
        float fr  = frBase + (float)j * 0.0625f;
        float frm = frmBase + (float)jm * 0.0625f;
        float2 u0, u1, u2, v0, v1, v2;
        eval_u(fr,  g_Bb[t],  om0, om1, om2, u0, u1, u2);
        eval_u(frm, g_Bb[tm], om0, om1, om2, v0, v1, v2);
        float h0x = 0.5f * (u0.x + v0.x), h0y = 0.5f * (u0.y - v0.y);
        float h1x = 0.5f * (u1.x + v1.x), h1y = 0.5f * (u1.y - v1.y);
        P[j] = make_float2(h0x - h1y, h0y + h1x);
        Q[j] = make_float2(0.5f * (u2.x + v2.x), 0.5f * (u2.y - v2.y));
    }

    float th0 = (float)(2.0 * PI_D / (double)TN);
    float sn, cs;
    __sincosf(th0 * (float)gid, &sn, &cs);
    float2 W[16];
    twiddle_powers(make_float2(cs, sn), W);
    int ob = gid << 4;

    fft16<false>(P);
    g_A[ob] = P[0];
#pragma unroll
    for (int r = 1; r < 16; r++) g_A[ob + r] = cmul(P[r], W[r]);

    fft16<false>(Q);
    g_A[TN + ob] = Q[0];
#pragma unroll
    for (int r = 1; r < 16; r++) g_A[TN + ob + r] = cmul(Q[r], W[r]);
}

// ---------------- final inverse stage fused with real output (reads g_Bb) ----------------
__global__ void __launch_bounds__(256) inv_final_kernel(float* __restrict__ out) {
    int gid = blockIdx.x * blockDim.x + threadIdx.x;   // 0..131071
    int q = gid & 65535;
    int b = gid >> 16;
    const float2* __restrict__ X = g_Bb + (b << LOG2TN);
    float2 z[16];
#pragma unroll
    for (int j = 0; j < 16; j++) z[j] = X[q + (j << 16)];
    fft16<false>(z);
    float sg = (q & 1) ? -(1.0f / 1048576.0f) : (1.0f / 1048576.0f);
    if (b == 0) {
#pragma unroll
        for (int r = 0; r < 16; r++) {
            out[q + (r << 16)]      = z[r].x * sg;   // y0 = Re
            out[TN + q + (r << 16)] = z[r].y * sg;   // y1 = Im
        }
    } else {
#pragma unroll
        for (int r = 0; r < 16; r++)
            out[2 * TN + q + (r << 16)] = z[r].x * sg;  // y2 = Re
    }
}

// ---------------- launch ----------------
extern "C" void kernel_launch(void* const* d_in, const int* in_sizes, int n_in,
                              void* d_out, int out_size) {
    const float* x   = (const float*)d_in[0];
    const float* om0 = (const float*)d_in[1];
    float* out = (float*)d_out;

    // forward FFT of (-1)^n x (stage 0 carries global init)
    fwd0_kernel<<<256, 256>>>(x, om0);
    for (int i = 1; i < 5; i++) {
        float th0 = (float)(-2.0 * PI_D * (double)(1 << (4 * i)) / (double)TN);
        fft16_stage<true><<<256, 256>>>(i & 1, 4 * i, th0);
    }

    hist_kernel<<<NBIN / 8, 256>>>();      // M2 weights -> 4096 bins
    vmd_iter_kernel<<<1, ITPB>>>();        // 50 omega iterations, one block

    ustage0_kernel<<<256, 256>>>();        // fhat -> u -> Hermitian pack + stage 0 -> g_A

    // inverse stages 1..3 (2 batches): A->B->A->B
    for (int i = 1; i < 4; i++) {
        float th0 = (float)(2.0 * PI_D * (double)(1 << (4 * i)) / (double)TN);
        fft16_stage<false><<<512, 256>>>(1 - (i & 1), 4 * i, th0);
    }
    // final stage fused with real output: batch0 -> y0 (Re), y1 (Im); batch1 -> y2 (Re)
    inv_final_kernel<<<512, 256>>>(out);
}

// round 16
// speedup vs baseline: 3.3604x; 1.0568x over previous
#include <cuda_runtime.h>

#define TN (1 << 20)
#define LOG2TN 20
#define KM 3
#define C_ALPHA 2000.0f
#define PI_D 3.14159265358979323846

typedef unsigned long long ull;

// ---------------- scratch (device globals; no allocation allowed) ----------------
__device__ float2 g_A[2 * TN];        // FFT ping buffer (2 batches)
__device__ float2 g_Bb[2 * TN];       // FFT pong buffer; [0..TN) holds fhat after fwd
#define NBIN 4096
__device__ float2 g_hist[NBIN];       // per-bin (S0 = sum M2, Sf = sum M2*fr)
__device__ float g_om[KM];

__device__ __forceinline__ float frcp(float x) {
    float r; asm("rcp.approx.f32 %0, %1;" : "=f"(r) : "f"(x)); return r;
}

// ---------------- complex helpers ----------------
__device__ __forceinline__ float2 cadd(float2 a, float2 b) { return make_float2(a.x + b.x, a.y + b.y); }
__device__ __forceinline__ float2 csub(float2 a, float2 b) { return make_float2(a.x - b.x, a.y - b.y); }
__device__ __forceinline__ float2 cmul(float2 a, float2 b) {
    return make_float2(a.x * b.x - a.y * b.y, a.x * b.y + a.y * b.x);
}

// twiddle powers W[1..15] from W1, binary tree (depth 4)
__device__ __forceinline__ void twiddle_powers(float2 W1, float2* W) {
    W[1] = W1;
    W[2]  = cmul(W1, W1);
    W[4]  = cmul(W[2], W[2]);
    W[8]  = cmul(W[4], W[4]);
    W[3]  = cmul(W[2], W1);
    W[5]  = cmul(W[4], W1);
    W[6]  = cmul(W[4], W[2]);
    W[7]  = cmul(W[4], W[3]);
    W[9]  = cmul(W[8], W1);
    W[10] = cmul(W[8], W[2]);
    W[11] = cmul(W[8], W[3]);
    W[12] = cmul(W[8], W[4]);
    W[13] = cmul(W[8], W[5]);
    W[14] = cmul(W[8], W[6]);
    W[15] = cmul(W[8], W[7]);
}

// ---------------- radix-16 butterfly ----------------
template <bool FWD>
__device__ __forceinline__ void bf4(float2 a, float2 b, float2 c, float2 d,
                                    float2& o0, float2& o1, float2& o2, float2& o3) {
    float2 apc = cadd(a, c), amc = csub(a, c);
    float2 bpd = cadd(b, d), bmd = csub(b, d);
    o0 = cadd(apc, bpd);
    o2 = csub(apc, bpd);
    if (FWD) {
        o1 = make_float2(amc.x + bmd.y, amc.y - bmd.x);
        o3 = make_float2(amc.x - bmd.y, amc.y + bmd.x);
    } else {
        o1 = make_float2(amc.x - bmd.y, amc.y + bmd.x);
        o3 = make_float2(amc.x + bmd.y, amc.y - bmd.x);
    }
}

template <bool FWD>
__device__ __forceinline__ void fft16(float2* z) {
    const float S  = FWD ? -1.f : 1.f;
    const float C1 = 0.92387953251128674f;
    const float S1 = 0.38268343236508977f;
    const float R  = 0.70710678118654752f;
    float2 A[16];
#pragma unroll
    for (int n1 = 0; n1 < 4; n1++)
        bf4<FWD>(z[n1], z[n1 + 4], z[n1 + 8], z[n1 + 12],
                 A[n1 * 4 + 0], A[n1 * 4 + 1], A[n1 * 4 + 2], A[n1 * 4 + 3]);
    A[5]  = cmul(A[5],  make_float2( C1,  S * S1));
    A[6]  = cmul(A[6],  make_float2( R,   S * R ));
    A[7]  = cmul(A[7],  make_float2( S1,  S * C1));
    A[9]  = cmul(A[9],  make_float2( R,   S * R ));
    A[10] = make_float2(-S * A[10].y, S * A[10].x);
    A[11] = cmul(A[11], make_float2(-R,   S * R ));
    A[13] = cmul(A[13], make_float2( S1,  S * C1));
    A[14] = cmul(A[14], make_float2(-R,   S * R ));
    A[15] = cmul(A[15], make_float2(-C1, -S * S1));
#pragma unroll
    for (int k2 = 0; k2 < 4; k2++)
        bf4<FWD>(A[k2], A[4 + k2], A[8 + k2], A[12 + k2],
                 z[k2], z[k2 + 4], z[k2 + 8], z[k2 + 12]);
}

// ---------------- forward stage 0 (radix-16, s=1) fused with (-1)^n pack + init ----------------
__global__ void __launch_bounds__(256) fwd0_kernel(const float* __restrict__ x,
                                                   const float* __restrict__ om0in) {
    if (blockIdx.x == 0 && threadIdx.x == 0) {
        g_om[0] = 0.5f * om0in[0]; g_om[1] = 0.5f * om0in[1]; g_om[2] = 0.5f * om0in[2];
    }
    int p = blockIdx.x * blockDim.x + threadIdx.x;
    float sgn = (p & 1) ? -1.f : 1.f;
    float2 z[16];
#pragma unroll
    for (int j = 0; j < 16; j++) z[j] = make_float2(sgn * x[p + j * 65536], 0.f);
    fft16<true>(z);
    float th0 = (float)(-2.0 * PI_D / (double)TN);
    float sn, cs;
    __sincosf(th0 * (float)p, &sn, &cs);
    float2 W[16];
    twiddle_powers(make_float2(cs, sn), W);
    int ob = p << 4;
    g_Bb[ob] = z[0];
#pragma unroll
    for (int r = 1; r < 16; r++) g_Bb[ob + r] = cmul(z[r], W[r]);
}

// ---------------- fused radix-256 Stockham stage (== two radix-16 stages) ----------------
// Block: 256 threads handle 16 butterflies x 256 points = 4096 elements.
// thread t: bb = t&15 (butterfly), hi = t>>4 (j1 in phase 1, r1 in phase 2).
// FINAL: inverse last stage (s=4096, p=0) fused with real output.
template <bool FWD, bool FINAL>
__global__ void __launch_bounds__(256) fftR256_stage(int inIsB, int log2s, float th0,
                                                     float* __restrict__ out) {
    int B = blockIdx.x & 255, batch = blockIdx.x >> 8;
    const float2* __restrict__ X = (inIsB ? g_Bb : g_A) + (batch << LOG2TN);
    float2* __restrict__       Y = (inIsB ? g_A : g_Bb) + (batch << LOG2TN);
    int t  = threadIdx.x;
    int bb = t & 15, hi = t >> 4;
    int tidb = (B << 4) + bb;
    int s  = 1 << log2s;
    int q  = tidb & (s - 1);
    int p  = tidb >> log2s;
    int m  = TN >> (log2s + 8);

    __shared__ float2 sm[16 * 257];

    // ---- phase 1: DFT16 over j2 for j1 = hi; internal twiddle w256^{S j1 r1} ----
    float2 z[16];
#pragma unroll
    for (int j2 = 0; j2 < 16; j2++)
        z[j2] = X[q + ((p + (hi + (j2 << 4)) * m) << log2s)];
    fft16<FWD>(z);
    {
        const float TH = FWD ? (float)(-2.0 * PI_D / 256.0) : (float)(2.0 * PI_D / 256.0);
        float sn, cs;
        __sincosf(TH * (float)hi, &sn, &cs);
        float2 W[16];
        twiddle_powers(make_float2(cs, sn), W);
#pragma unroll
        for (int r1 = 1; r1 < 16; r1++) z[r1] = cmul(z[r1], W[r1]);
    }
#pragma unroll
    for (int r1 = 0; r1 < 16; r1++) sm[bb * 257 + r1 * 16 + hi] = z[r1];
    __syncthreads();

    // ---- phase 2: DFT16 over j1 for r1 = hi ----
    float2 A[16];
#pragma unroll
    for (int j1 = 0; j1 < 16; j1++) A[j1] = sm[bb * 257 + hi * 16 + j1];
    fft16<FWD>(A);

    if (!FINAL) {
        // stage twiddle exp(S*2pi*p*(r1 + 16 r2)*s/N); th0 = S*2pi*s/N
        float a1 = th0 * (float)p;
        float sn, cs;
        __sincosf(a1 * (float)hi, &sn, &cs);
        float2 c1 = make_float2(cs, sn);
        __sincosf(a1 * 16.0f, &sn, &cs);
        float2 W[16];
        twiddle_powers(make_float2(cs, sn), W);
        int ob = q + (((p << 8) + hi) << log2s);
        Y[ob] = cmul(A[0], c1);
#pragma unroll
        for (int r2 = 1; r2 < 16; r2++)
            Y[ob + (r2 << (log2s + 4))] = cmul(A[r2], cmul(W[r2], c1));
    } else {
        // inverse last stage: s=4096, p=0, no twiddle; out = Re/Im * (-1)^t / TN
        float sg = (q & 1) ? -(1.0f / 1048576.0f) : (1.0f / 1048576.0f);
        int ob = q + (hi << 12);
        if (batch == 0) {
#pragma unroll
            for (int r2 = 0; r2 < 16; r2++) {
                int tt = ob + (r2 << 16);
                out[tt]      = A[r2].x * sg;   // y0 = Re
                out[TN + tt] = A[r2].y * sg;   // y1 = Im
            }
        } else {
#pragma unroll
            for (int r2 = 0; r2 < 16; r2++)
                out[2 * TN + ob + (r2 << 16)] = A[r2].x * sg;  // y2 = Re
        }
    }
}

// ---------------- histogram: M2 weights onto NBIN bins (deterministic, warp/bin) ----------------
__global__ void __launch_bounds__(256) hist_kernel() {
    int warp = (blockIdx.x << 3) + (threadIdx.x >> 5);   // 512 blocks x 8 warps = 4096 bins
    int lane = threadIdx.x & 31;
    int base = warp << 8;                                 // 256 elements per bin
    const float FRC = 1.0f / 1048576.0f;
    float s0 = 0.f, sf = 0.f;
#pragma unroll
    for (int i = 0; i < 8; i++) {
        int t = base + lane + (i << 5);
        float2 v = g_Bb[t];
        float m2 = v.x * v.x + v.y * v.y;
        float fr = fmaf((float)t, FRC, -0.5f);
        s0 += m2;
        sf = fmaf(m2, fr, sf);
    }
#pragma unroll
    for (int o = 16; o; o >>= 1) {
        s0 += __shfl_down_sync(0xffffffffu, s0, o);
        sf += __shfl_down_sync(0xffffffffu, sf, o);
    }
    if (lane == 0) g_hist[warp] = make_float2(s0, sf);
}

// ---------------- 50 VMD iterations in ONE block over the histogram ----------------
#define ITPB 1024
#define PB (NBIN / ITPB)   // 4 bins per thread

__global__ void __launch_bounds__(ITPB) vmd_iter_kernel() {
    int tid = threadIdx.x;
    int wid = tid >> 5, lid = tid & 31;

    float S0[PB], Sf[PB], Fb[PB];
#pragma unroll
    for (int j = 0; j < PB; j++) {
        float2 h = g_hist[tid + j * ITPB];
        S0[j] = h.x; Sf[j] = h.y;
        Fb[j] = h.y * frcp(h.x + 1e-30f);    // M2-centroid of the bin
    }
    float om0 = g_om[0], om1 = g_om[1], om2 = g_om[2];
    float oD0 = om0, oD1 = om1, oD2 = om2;

    __shared__ float sred[8][ITPB / 32];
    __shared__ float sIt[8];
    __shared__ float sOm[3];
    __shared__ int   sTerm;
    __shared__ int   sStashOK;
    if (tid == 0) sStashOK = 0;
    __syncthreads();

    int stashedPrev = 0;

    for (int n = 0; n < 50; n++) {
        float a0 = 0.f, a1 = 0.f, a2 = 0.f, a3 = 0.f, a4 = 0.f, a5 = 0.f, a6 = 0.f, a7 = 0.f;
        bool doDiff = (n > 0) && (n % 10 == 0) && stashedPrev;

#pragma unroll
        for (int j = 0; j < PB; j++) {
            float f = Fb[j];
            float d0 = f - om0; d0 *= d0;
            float d1 = f - om1; d1 *= d1;
            float d2 = f - om2; d2 *= d2;
            float g0 = frcp(fmaf(C_ALPHA, d0 + d1, 1.0f));
            float g1 = frcp(fmaf(C_ALPHA, (d1 + d0) + d2, 1.0f));
            float g2 = frcp(fmaf(C_ALPHA, d2 + d1, 1.0f));
            float p0 = g0 * g0, p1 = g1 * g1, p2 = g2 * g2;
            a0 = fmaf(p0, S0[j], a0); a1 = fmaf(p1, S0[j], a1); a2 = fmaf(p2, S0[j], a2);
            a3 = fmaf(p0, Sf[j], a3); a4 = fmaf(p1, Sf[j], a4); a5 = fmaf(p2, Sf[j], a5);
            if (doDiff) {
                float q0 = f - oD0; q0 *= q0;
                float q1 = f - oD1; q1 *= q1;
                float q2 = f - oD2; q2 *= q2;
                float h0 = frcp(fmaf(C_ALPHA, q0 + q1, 1.0f));
                float h1 = frcp(fmaf(C_ALPHA, (q1 + q0) + q2, 1.0f));
                float h2 = frcp(fmaf(C_ALPHA, q2 + q1, 1.0f));
                float e0 = g0 - h0, e1 = g1 - h1, e2 = g2 - h2;
                a6 = fmaf(S0[j], e0 * e0 + e1 * e1 + e2 * e2, a6);
                a7 = fmaf(S0[j], h0 * h0 + h1 * h1 + h2 * h2, a7);
            }
        }

        float vals[8] = {a0, a1, a2, a3, a4, a5, a6, a7};
#pragma unroll
        for (int i = 0; i < 8; i++) {
            float v = vals[i];
#pragma unroll
            for (int o = 16; o > 0; o >>= 1) v += __shfl_down_sync(0xffffffffu, v, o);
            vals[i] = v;
        }
        if (lid == 0) {
#pragma unroll
            for (int i = 0; i < 8; i++) sred[i][wid] = vals[i];
        }
        __syncthreads();
        if (tid < 8) {
            float s = 0.f;
#pragma unroll
            for (int w = 0; w < ITPB / 32; w++) s += sred[tid][w];
            sIt[tid] = s;
        }
        __syncthreads();
        if (tid == 0) {
            float it0 = sIt[0], it1 = sIt[1], it2 = sIt[2];
            float on0 = sIt[3] / (it0 + 1e-8f);
            float on1 = sIt[4] / (it1 + 1e-8f);
            float on2 = sIt[5] / (it2 + 1e-8f);
            float odiff = (fabsf(on0 - on2) + fabsf(on1 - on0) + fabsf(on2 - on1)) * (1.0f / 3.0f);
            float udiff;
            if (n == 0)                              udiff = (it0 + it1 + it2) * 1e8f;
            else if (stashedPrev && (n % 10 == 0))   udiff = sIt[6] / (sIt[7] + 1e-8f);
            else                                     udiff = 1e30f;
            int done = (n % 10 == 0) && (udiff < 1e-6f) && (odiff < 1e-6f);
            sOm[0] = on0; sOm[1] = on1; sOm[2] = on2;
            sStashOK = (odiff < 1e-2f) ? 1 : 0;
            sTerm = (done || n == 49) ? 1 : 0;
        }
        __syncthreads();

        stashedPrev = ((n % 10 == 9) && (n < 49) && (sStashOK != 0)) ? 1 : 0;

        if (sTerm) {
            if (tid == 0) { g_om[0] = om0; g_om[1] = om1; g_om[2] = om2; }
            break;
        }
        oD0 = om0; oD1 = om1; oD2 = om2;
        om0 = sOm[0]; om1 = sOm[1]; om2 = sOm[2];
        __syncthreads();
    }
}

// ---------------- u + Hermitian pack + inverse stage 0 (radix-16, s=1) ----------------
__device__ __forceinline__ void eval_u(float fr, float2 fh,
                                       float om0, float om1, float om2,
                                       float2& u0, float2& u1, float2& u2) {
    float d0 = fr - om0; d0 *= d0;
    float d1 = fr - om1; d1 *= d1;
    float d2 = fr - om2; d2 *= d2;
    float g0 = frcp(fmaf(C_ALPHA, d0 + d1, 1.0f));
    float g1 = frcp(fmaf(C_ALPHA, (d1 + d0) + d2, 1.0f));
    float g2 = frcp(fmaf(C_ALPHA, d2 + d1, 1.0f));
    u0 = make_float2(fh.x * g0, fh.y * g0);
    u1 = make_float2(fh.x * g1, fh.y * g1);
    u2 = make_float2(fh.x * g2, fh.y * g2);
}

__global__ void __launch_bounds__(256) ustage0_kernel() {
    int gid = blockIdx.x * blockDim.x + threadIdx.x;   // 0..65535
    float om0 = g_om[0], om1 = g_om[1], om2 = g_om[2];
    const float FRC = 1.0f / 1048576.0f;
    float frBase = fmaf((float)gid, FRC, -0.5f);
    int gm = (65536 - gid) & 65535;
    float frmBase = fmaf((float)gm, FRC, -0.5f);

    float2 P[16], Q[16];
#pragma unroll
    for (int j = 0; j < 16; j++) {
        int t  = j * 65536 + gid;
        int jm = (gid == 0) ? ((16 - j) & 15) : (15 - j);
        int tm = jm * 65536 + gm;
        float fr  = frBase + (float)j * 0.0625f;
        float frm = frmBase + (float)jm * 0.0625f;
        float2 u0, u1, u2, v0, v1, v2;
        eval_u(fr,  g_Bb[t],  om0, om1, om2, u0, u1, u2);
        eval_u(frm, g_Bb[tm], om0, om1, om2, v0, v1, v2);
        float h0x = 0.5f * (u0.x + v0.x), h0y = 0.5f * (u0.y - v0.y);
        float h1x = 0.5f * (u1.x + v1.x), h1y = 0.5f * (u1.y - v1.y);
        P[j] = make_float2(h0x - h1y, h0y + h1x);
        Q[j] = make_float2(0.5f * (u2.x + v2.x), 0.5f * (u2.y - v2.y));
    }

    float th0 = (float)(2.0 * PI_D / (double)TN);
    float sn, cs;
    __sincosf(th0 * (float)gid, &sn, &cs);
    float2 W[16];
    twiddle_powers(make_float2(cs, sn), W);
    int ob = gid << 4;

    fft16<false>(P);
    g_A[ob] = P[0];
#pragma unroll
    for (int r = 1; r < 16; r++) g_A[ob + r] = cmul(P[r], W[r]);

    fft16<false>(Q);
    g_A[TN + ob] = Q[0];
#pragma unroll
    for (int r = 1; r < 16; r++) g_A[TN + ob + r] = cmul(Q[r], W[r]);
}

// ---------------- launch ----------------
extern "C" void kernel_launch(void* const* d_in, const int* in_sizes, int n_in,
                              void* d_out, int out_size) {
    const float* x   = (const float*)d_in[0];
    const float* om0 = (const float*)d_in[1];
    float* out = (float*)d_out;

    float thF16 = (float)(-2.0 * PI_D * 16.0 / (double)TN);
    float thI16 = (float)( 2.0 * PI_D * 16.0 / (double)TN);

    // forward: radix-16 (s=1, fused pack) + radix-256 (s=16) + radix-256 (s=4096) -> g_Bb
    fwd0_kernel<<<256, 256>>>(x, om0);
    fftR256_stage<true,  false><<<256, 256>>>(1, 4, thF16, nullptr);   // B -> A
    fftR256_stage<true,  false><<<256, 256>>>(0, 12, 0.f, nullptr);    // A -> B (p=0)

    hist_kernel<<<NBIN / 8, 256>>>();      // M2 weights -> 4096 bins
    vmd_iter_kernel<<<1, ITPB>>>();        // 50 omega iterations, one block

    // inverse: ustage0 (s=1, fused u-gen+pack) + radix-256 (s=16) + radix-256 (s=4096, output)
    ustage0_kernel<<<256, 256>>>();                                     // B -> A (2 batches)
    fftR256_stage<false, false><<<512, 256>>>(0, 4, thI16, nullptr);    // A -> B
    fftR256_stage<false, true ><<<512, 256>>>(1, 12, 0.f, out);         // B -> out
}

// round 17
// speedup vs baseline: 4.6220x; 1.3754x over previous
#include <cuda_runtime.h>

#define TN (1 << 20)
#define LOG2TN 20
#define KM 3
#define C_ALPHA 2000.0f
#define PI_D 3.14159265358979323846

typedef unsigned long long ull;

// ---------------- scratch (device globals; no allocation allowed) ----------------
__device__ float2 g_A[2 * TN];        // FFT ping buffer (2 batches)
__device__ float2 g_Bb[2 * TN];       // FFT pong buffer; [0..TN) holds fhat after fwd
#define NBIN 2048
__device__ float2 g_hist[NBIN];       // per-bin (S0 = sum M2, Sf = sum M2*fr)
__device__ float g_om[KM];

__device__ __forceinline__ float frcp(float x) {
    float r; asm("rcp.approx.f32 %0, %1;" : "=f"(r) : "f"(x)); return r;
}

// ---------------- complex helpers ----------------
__device__ __forceinline__ float2 cadd(float2 a, float2 b) { return make_float2(a.x + b.x, a.y + b.y); }
__device__ __forceinline__ float2 csub(float2 a, float2 b) { return make_float2(a.x - b.x, a.y - b.y); }
__device__ __forceinline__ float2 cmul(float2 a, float2 b) {
    return make_float2(a.x * b.x - a.y * b.y, a.x * b.y + a.y * b.x);
}

// twiddle powers W[1..15] from W1, binary tree (depth 4)
__device__ __forceinline__ void twiddle_powers(float2 W1, float2* W) {
    W[1] = W1;
    W[2]  = cmul(W1, W1);
    W[4]  = cmul(W[2], W[2]);
    W[8]  = cmul(W[4], W[4]);
    W[3]  = cmul(W[2], W1);
    W[5]  = cmul(W[4], W1);
    W[6]  = cmul(W[4], W[2]);
    W[7]  = cmul(W[4], W[3]);
    W[9]  = cmul(W[8], W1);
    W[10] = cmul(W[8], W[2]);
    W[11] = cmul(W[8], W[3]);
    W[12] = cmul(W[8], W[4]);
    W[13] = cmul(W[8], W[5]);
    W[14] = cmul(W[8], W[6]);
    W[15] = cmul(W[8], W[7]);
}

// ---------------- radix-16 butterfly ----------------
template <bool FWD>
__device__ __forceinline__ void bf4(float2 a, float2 b, float2 c, float2 d,
                                    float2& o0, float2& o1, float2& o2, float2& o3) {
    float2 apc = cadd(a, c), amc = csub(a, c);
    float2 bpd = cadd(b, d), bmd = csub(b, d);
    o0 = cadd(apc, bpd);
    o2 = csub(apc, bpd);
    if (FWD) {
        o1 = make_float2(amc.x + bmd.y, amc.y - bmd.x);
        o3 = make_float2(amc.x - bmd.y, amc.y + bmd.x);
    } else {
        o1 = make_float2(amc.x - bmd.y, amc.y + bmd.x);
        o3 = make_float2(amc.x + bmd.y, amc.y - bmd.x);
    }
}

template <bool FWD>
__device__ __forceinline__ void fft16(float2* z) {
    const float S  = FWD ? -1.f : 1.f;
    const float C1 = 0.92387953251128674f;
    const float S1 = 0.38268343236508977f;
    const float R  = 0.70710678118654752f;
    float2 A[16];
#pragma unroll
    for (int n1 = 0; n1 < 4; n1++)
        bf4<FWD>(z[n1], z[n1 + 4], z[n1 + 8], z[n1 + 12],
                 A[n1 * 4 + 0], A[n1 * 4 + 1], A[n1 * 4 + 2], A[n1 * 4 + 3]);
    A[5]  = cmul(A[5],  make_float2( C1,  S * S1));
    A[6]  = cmul(A[6],  make_float2( R,   S * R ));
    A[7]  = cmul(A[7],  make_float2( S1,  S * C1));
    A[9]  = cmul(A[9],  make_float2( R,   S * R ));
    A[10] = make_float2(-S * A[10].y, S * A[10].x);
    A[11] = cmul(A[11], make_float2(-R,   S * R ));
    A[13] = cmul(A[13], make_float2( S1,  S * C1));
    A[14] = cmul(A[14], make_float2(-R,   S * R ));
    A[15] = cmul(A[15], make_float2(-C1, -S * S1));
#pragma unroll
    for (int k2 = 0; k2 < 4; k2++)
        bf4<FWD>(A[k2], A[4 + k2], A[8 + k2], A[12 + k2],
                 z[k2], z[k2 + 4], z[k2 + 8], z[k2 + 12]);
}

// ---------------- forward stage 0 (radix-16, s=1) fused with (-1)^n pack + init ----------------
__global__ void __launch_bounds__(256) fwd0_kernel(const float* __restrict__ x,
                                                   const float* __restrict__ om0in) {
    if (blockIdx.x == 0 && threadIdx.x == 0) {
        g_om[0] = 0.5f * om0in[0]; g_om[1] = 0.5f * om0in[1]; g_om[2] = 0.5f * om0in[2];
    }
    int p = blockIdx.x * blockDim.x + threadIdx.x;
    float sgn = (p & 1) ? -1.f : 1.f;
    float2 z[16];
#pragma unroll
    for (int j = 0; j < 16; j++) z[j] = make_float2(sgn * x[p + j * 65536], 0.f);
    fft16<true>(z);
    float th0 = (float)(-2.0 * PI_D / (double)TN);
    float sn, cs;
    __sincosf(th0 * (float)p, &sn, &cs);
    float2 W[16];
    twiddle_powers(make_float2(cs, sn), W);
    int ob = p << 4;
    g_Bb[ob] = z[0];
#pragma unroll
    for (int r = 1; r < 16; r++) g_Bb[ob + r] = cmul(z[r], W[r]);
}

// ---------------- fused radix-256 Stockham stage (== two radix-16 stages) ----------------
template <bool FWD, bool FINAL>
__global__ void __launch_bounds__(256) fftR256_stage(int inIsB, int log2s, float th0,
                                                     float* __restrict__ out) {
    int B = blockIdx.x & 255, batch = blockIdx.x >> 8;
    const float2* __restrict__ X = (inIsB ? g_Bb : g_A) + (batch << LOG2TN);
    float2* __restrict__       Y = (inIsB ? g_A : g_Bb) + (batch << LOG2TN);
    int t  = threadIdx.x;
    int bb = t & 15, hi = t >> 4;
    int tidb = (B << 4) + bb;
    int s  = 1 << log2s;
    int q  = tidb & (s - 1);
    int p  = tidb >> log2s;
    int m  = TN >> (log2s + 8);

    __shared__ float2 sm[16 * 257];

    float2 z[16];
#pragma unroll
    for (int j2 = 0; j2 < 16; j2++)
        z[j2] = X[q + ((p + (hi + (j2 << 4)) * m) << log2s)];
    fft16<FWD>(z);
    {
        const float TH = FWD ? (float)(-2.0 * PI_D / 256.0) : (float)(2.0 * PI_D / 256.0);
        float sn, cs;
        __sincosf(TH * (float)hi, &sn, &cs);
        float2 W[16];
        twiddle_powers(make_float2(cs, sn), W);
#pragma unroll
        for (int r1 = 1; r1 < 16; r1++) z[r1] = cmul(z[r1], W[r1]);
    }
#pragma unroll
    for (int r1 = 0; r1 < 16; r1++) sm[bb * 257 + r1 * 16 + hi] = z[r1];
    __syncthreads();

    float2 A[16];
#pragma unroll
    for (int j1 = 0; j1 < 16; j1++) A[j1] = sm[bb * 257 + hi * 16 + j1];
    fft16<FWD>(A);

    if (!FINAL) {
        float a1 = th0 * (float)p;
        float sn, cs;
        __sincosf(a1 * (float)hi, &sn, &cs);
        float2 c1 = make_float2(cs, sn);
        __sincosf(a1 * 16.0f, &sn, &cs);
        float2 W[16];
        twiddle_powers(make_float2(cs, sn), W);
        int ob = q + (((p << 8) + hi) << log2s);
        Y[ob] = cmul(A[0], c1);
#pragma unroll
        for (int r2 = 1; r2 < 16; r2++)
            Y[ob + (r2 << (log2s + 4))] = cmul(A[r2], cmul(W[r2], c1));
    } else {
        float sg = (q & 1) ? -(1.0f / 1048576.0f) : (1.0f / 1048576.0f);
        int ob = q + (hi << 12);
        if (batch == 0) {
#pragma unroll
            for (int r2 = 0; r2 < 16; r2++) {
                int tt = ob + (r2 << 16);
                out[tt]      = A[r2].x * sg;   // y0 = Re
                out[TN + tt] = A[r2].y * sg;   // y1 = Im
            }
        } else {
#pragma unroll
            for (int r2 = 0; r2 < 16; r2++)
                out[2 * TN + ob + (r2 << 16)] = A[r2].x * sg;  // y2 = Re
        }
    }
}

// ---------------- histogram: M2 weights onto NBIN bins (deterministic, warp/bin) ----------------
__global__ void __launch_bounds__(256) hist_kernel() {
    int warp = (blockIdx.x << 3) + (threadIdx.x >> 5);   // 256 blocks x 8 warps = 2048 bins
    int lane = threadIdx.x & 31;
    int base = warp << 9;                                 // 512 elements per bin
    const float FRC = 1.0f / 1048576.0f;
    float s0 = 0.f, sf = 0.f;
#pragma unroll
    for (int i = 0; i < 16; i++) {
        int t = base + lane + (i << 5);
        float2 v = g_Bb[t];
        float m2 = v.x * v.x + v.y * v.y;
        float fr = fmaf((float)t, FRC, -0.5f);
        s0 += m2;
        sf = fmaf(m2, fr, sf);
    }
#pragma unroll
    for (int o = 16; o; o >>= 1) {
        s0 += __shfl_down_sync(0xffffffffu, s0, o);
        sf += __shfl_down_sync(0xffffffffu, sf, o);
    }
    if (lane == 0) g_hist[warp] = make_float2(s0, sf);
}

// ---------------- 50 VMD iterations in ONE block over the histogram ----------------
#define ITPB 512
#define PB (NBIN / ITPB)   // 4 bins per thread

__global__ void __launch_bounds__(ITPB) vmd_iter_kernel() {
    int tid = threadIdx.x;
    int wid = tid >> 5, lid = tid & 31;

    float S0[PB], Sf[PB], Fb[PB];
#pragma unroll
    for (int j = 0; j < PB; j++) {
        float2 h = g_hist[tid + j * ITPB];
        S0[j] = h.x; Sf[j] = h.y;
        Fb[j] = h.y * frcp(h.x + 1e-30f);    // M2-centroid of the bin
    }
    float om0 = g_om[0], om1 = g_om[1], om2 = g_om[2];
    float oD0 = om0, oD1 = om1, oD2 = om2;

    __shared__ float sred[8][ITPB / 32];
    __shared__ float sIt[8];
    __shared__ float sOm[3];
    __shared__ int   sTerm;
    __shared__ int   sStashOK;
    if (tid == 0) sStashOK = 0;
    __syncthreads();

    int stashedPrev = 0;

    for (int n = 0; n < 50; n++) {
        float a0 = 0.f, a1 = 0.f, a2 = 0.f, a3 = 0.f, a4 = 0.f, a5 = 0.f, a6 = 0.f, a7 = 0.f;
        bool doDiff = (n > 0) && (n % 10 == 0) && stashedPrev;

#pragma unroll
        for (int j = 0; j < PB; j++) {
            float f = Fb[j];
            float d0 = f - om0; d0 *= d0;
            float d1 = f - om1; d1 *= d1;
            float d2 = f - om2; d2 *= d2;
            float g0 = frcp(fmaf(C_ALPHA, d0 + d1, 1.0f));
            float g1 = frcp(fmaf(C_ALPHA, (d1 + d0) + d2, 1.0f));
            float g2 = frcp(fmaf(C_ALPHA, d2 + d1, 1.0f));
            float p0 = g0 * g0, p1 = g1 * g1, p2 = g2 * g2;
            a0 = fmaf(p0, S0[j], a0); a1 = fmaf(p1, S0[j], a1); a2 = fmaf(p2, S0[j], a2);
            a3 = fmaf(p0, Sf[j], a3); a4 = fmaf(p1, Sf[j], a4); a5 = fmaf(p2, Sf[j], a5);
            if (doDiff) {
                float q0 = f - oD0; q0 *= q0;
                float q1 = f - oD1; q1 *= q1;
                float q2 = f - oD2; q2 *= q2;
                float h0 = frcp(fmaf(C_ALPHA, q0 + q1, 1.0f));
                float h1 = frcp(fmaf(C_ALPHA, (q1 + q0) + q2, 1.0f));
                float h2 = frcp(fmaf(C_ALPHA, q2 + q1, 1.0f));
                float e0 = g0 - h0, e1 = g1 - h1, e2 = g2 - h2;
                a6 = fmaf(S0[j], e0 * e0 + e1 * e1 + e2 * e2, a6);
                a7 = fmaf(S0[j], h0 * h0 + h1 * h1 + h2 * h2, a7);
            }
        }

        float vals[8] = {a0, a1, a2, a3, a4, a5, a6, a7};
#pragma unroll
        for (int i = 0; i < 8; i++) {
            float v = vals[i];
#pragma unroll
            for (int o = 16; o > 0; o >>= 1) v += __shfl_down_sync(0xffffffffu, v, o);
            vals[i] = v;
        }
        if (lid == 0) {
#pragma unroll
            for (int i = 0; i < 8; i++) sred[i][wid] = vals[i];
        }
        __syncthreads();
        if (tid < 8) {
            float s = 0.f;
#pragma unroll
            for (int w = 0; w < ITPB / 32; w++) s += sred[tid][w];
            sIt[tid] = s;
        }
        __syncthreads();
        if (tid == 0) {
            float it0 = sIt[0], it1 = sIt[1], it2 = sIt[2];
            float on0 = sIt[3] / (it0 + 1e-8f);
            float on1 = sIt[4] / (it1 + 1e-8f);
            float on2 = sIt[5] / (it2 + 1e-8f);
            float odiff = (fabsf(on0 - on2) + fabsf(on1 - on0) + fabsf(on2 - on1)) * (1.0f / 3.0f);
            float udiff;
            if (n == 0)                              udiff = (it0 + it1 + it2) * 1e8f;
            else if (stashedPrev && (n % 10 == 0))   udiff = sIt[6] / (sIt[7] + 1e-8f);
            else                                     udiff = 1e30f;
            int done = (n % 10 == 0) && (udiff < 1e-6f) && (odiff < 1e-6f);
            sOm[0] = on0; sOm[1] = on1; sOm[2] = on2;
            sStashOK = (odiff < 1e-2f) ? 1 : 0;
            sTerm = (done || n == 49) ? 1 : 0;
        }
        __syncthreads();

        stashedPrev = ((n % 10 == 9) && (n < 49) && (sStashOK != 0)) ? 1 : 0;

        if (sTerm) {
            if (tid == 0) { g_om[0] = om0; g_om[1] = om1; g_om[2] = om2; }
            break;
        }
        oD0 = om0; oD1 = om1; oD2 = om2;
        om0 = sOm[0]; om1 = sOm[1]; om2 = sOm[2];
        __syncthreads();
    }
}

// ---------------- u + Hermitian pack + inverse stage 0 (radix-16, s=1) ----------------
__device__ __forceinline__ void eval_u(float fr, float2 fh,
                                       float om0, float om1, float om2,
                                       float2& u0, float2& u1, float2& u2) {
    float d0 = fr - om0; d0 *= d0;
    float d1 = fr - om1; d1 *= d1;
    float d2 = fr - om2; d2 *= d2;
    float g0 = frcp(fmaf(C_ALPHA, d0 + d1, 1.0f));
    float g1 = frcp(fmaf(C_ALPHA, (d1 + d0) + d2, 1.0f));
    float g2 = frcp(fmaf(C_ALPHA, d2 + d1, 1.0f));
    u0 = make_float2(fh.x * g0, fh.y * g0);
    u1 = make_float2(fh.x * g1, fh.y * g1);
    u2 = make_float2(fh.x * g2, fh.y * g2);
}

__global__ void __launch_bounds__(256) ustage0_kernel() {
    int gid = blockIdx.x * blockDim.x + threadIdx.x;   // 0..65535
    float om0 = g_om[0], om1 = g_om[1], om2 = g_om[2];
    const float FRC = 1.0f / 1048576.0f;
    float frBase = fmaf((float)gid, FRC, -0.5f);
    int gm = (65536 - gid) & 65535;
    float frmBase = fmaf((float)gm, FRC, -0.5f);

    float2 P[16], Q[16];
#pragma unroll
    for (int j = 0; j < 16; j++) {
        int t  = j * 65536 + gid;
        int jm = (gid == 0) ? ((16 - j) & 15) : (15 - j);
        int tm = jm * 65536 + gm;
        float fr  = frBase + (float)j * 0.0625f;
        float frm = frmBase + (float)jm * 0.0625f;
        float2 u0, u1, u2, v0, v1, v2;
        eval_u(fr,  g_Bb[t],  om0, om1, om2, u0, u1, u2);
        eval_u(frm, g_Bb[tm], om0, om1, om2, v0, v1, v2);
        float h0x = 0.5f * (u0.x + v0.x), h0y = 0.5f * (u0.y - v0.y);
        float h1x = 0.5f * (u1.x + v1.x), h1y = 0.5f * (u1.y - v1.y);
        P[j] = make_float2(h0x - h1y, h0y + h1x);
        Q[j] = make_float2(0.5f * (u2.x + v2.x), 0.5f * (u2.y - v2.y));
    }

    float th0 = (float)(2.0 * PI_D / (double)TN);
    float sn, cs;
    __sincosf(th0 * (float)gid, &sn, &cs);
    float2 W[16];
    twiddle_powers(make_float2(cs, sn), W);
    int ob = gid << 4;

    fft16<false>(P);
    g_A[ob] = P[0];
#pragma unroll
    for (int r = 1; r < 16; r++) g_A[ob + r] = cmul(P[r], W[r]);

    fft16<false>(Q);
    g_A[TN + ob] = Q[0];
#pragma unroll
    for (int r = 1; r < 16; r++) g_A[TN + ob + r] = cmul(Q[r], W[r]);
}

// ---------------- launch ----------------
extern "C" void kernel_launch(void* const* d_in, const int* in_sizes, int n_in,
                              void* d_out, int out_size) {
    const float* x   = (const float*)d_in[0];
    const float* om0 = (const float*)d_in[1];
    float* out = (float*)d_out;

    float thF16 = (float)(-2.0 * PI_D * 16.0 / (double)TN);
    float thI16 = (float)( 2.0 * PI_D * 16.0 / (double)TN);

    // forward: radix-16 (s=1, fused pack) + radix-256 (s=16) + radix-256 (s=4096) -> g_Bb
    fwd0_kernel<<<256, 256>>>(x, om0);
    fftR256_stage<true,  false><<<256, 256>>>(1, 4, thF16, nullptr);   // B -> A
    fftR256_stage<true,  false><<<256, 256>>>(0, 12, 0.f, nullptr);    // A -> B (p=0)

    hist_kernel<<<NBIN / 8, 256>>>();      // M2 weights -> 2048 bins
    vmd_iter_kernel<<<1, ITPB>>>();        // 50 omega iterations, one block

    // inverse: ustage0 (s=1, fused u-gen+pack) + radix-256 (s=16) + radix-256 (s=4096, output)
    ustage0_kernel<<<256, 256>>>();                                     // B -> A (2 batches)
    fftR256_stage<false, false><<<512, 256>>>(0, 4, thI16, nullptr);    // A -> B
    fftR256_stage<false, true ><<<512, 256>>>(1, 12, 0.f, out);         // B -> out
}